// round 14
// baseline (speedup 1.0000x reference)
#include <cuda_runtime.h>
#include <cuda_bf16.h>
#include <cstdint>
#include <math.h>

// Problem constants
#define Tn   3
#define Bn   16384
#define Dn   256
#define Hn   8
#define DHn  32
#define NLn  2
#define FFn  1024
#define NG   (Tn*Bn)        // 49152 row-groups
#define MROWS (NG*3)        // 147456 total rows
#define SCALE_F 0.17677669529663687f   // 1/sqrt(32)

typedef __nv_bfloat16 bf16;

// ---------------- device scratch (allocation-free) ----------------
__device__ float g_x[MROWS*Dn];                 // residual stream (fp32)
__device__ bf16  g_h[MROWS*Dn];                 // LN output (bf16)
__device__ bf16  g_qkv[(size_t)MROWS*3*Dn];     // fused QKV output (bf16)
__device__ bf16  g_o[MROWS*Dn];                 // attention output (bf16)
__device__ bf16  g_f[(size_t)MROWS*FFn];        // FFN intermediate (bf16)
#define WT_LAYER 786432
__device__ bf16  g_wt[2*WT_LAYER];
__device__ float g_bqkv[2*3*Dn];                // concatenated qkv bias, both layers

// =================== helpers ===================
__device__ __forceinline__ uint32_t smem_u32(const void* p) {
    uint32_t a;
    asm("{ .reg .u64 t; cvta.to.shared.u64 t, %1; cvt.u32.u64 %0, t; }" : "=r"(a) : "l"(p));
    return a;
}
#define CP_ASYNC16(dst, src) \
    asm volatile("cp.async.cg.shared.global [%0], [%1], 16;" :: "r"(dst), "l"(src) : "memory")
#define CP_COMMIT() asm volatile("cp.async.commit_group;" ::: "memory")
#define CP_WAIT0()  asm volatile("cp.async.wait_group 0;" ::: "memory")
#define CP_WAIT1()  asm volatile("cp.async.wait_group 1;" ::: "memory")

#define LDSM_X4(r0, r1, r2, r3, addr) \
    asm volatile("ldmatrix.sync.aligned.m8n8.x4.shared.b16 {%0,%1,%2,%3}, [%4];" \
        : "=r"(r0), "=r"(r1), "=r"(r2), "=r"(r3) : "r"(addr))

// mma.sync m16n8k16 bf16
__device__ __forceinline__ void mma_bf16(float* c, const uint32_t* a, const uint32_t* b) {
    asm volatile(
        "mma.sync.aligned.m16n8k16.row.col.f32.bf16.bf16.f32 "
        "{%0,%1,%2,%3}, {%4,%5,%6,%7}, {%8,%9}, {%0,%1,%2,%3};"
        : "+f"(c[0]), "+f"(c[1]), "+f"(c[2]), "+f"(c[3])
        : "r"(a[0]), "r"(a[1]), "r"(a[2]), "r"(a[3]), "r"(b[0]), "r"(b[1]));
}

#define KC   64
#define LDSB 72

// ======== LARGE kernel: 128x256 tile, 256 thr, 1 CTA/SM — used for EPILN GEMMs ========
#define NSTG 3
static constexpr int TILE_A_BF = 128 * LDSB;              // 9216
static constexpr int TILE_B_BF = 256 * LDSB;              // 18432
static constexpr int STAGE_BF  = TILE_A_BF + TILE_B_BF;   // 27648
static constexpr int STAGE_BYTES = STAGE_BF * 2;          // 55296
static constexpr int GEMM_SMEM_BYTES = NSTG * STAGE_BYTES; // 165888

template<int ACT, bool RESID, bool OBF, bool EPILN>
__global__ __launch_bounds__(256)
void gemm_tc(const bf16* __restrict__ A, int lda,
             const bf16* __restrict__ Bt,
             const float* __restrict__ bias,
             const float* __restrict__ resid,
             void* __restrict__ Cv, int ldc, int K,
             const float* __restrict__ lng, const float* __restrict__ lnb,
             bf16* __restrict__ hout) {
    extern __shared__ bf16 smem[];
    const uint32_t sbase = smem_u32(smem);
    const int tid = threadIdx.x;
    const int wid = tid >> 5, lane = tid & 31;
    const int wr = wid >> 2, wn = wid & 3;      // 2x4 warp grid (M x N)
    const int gr = lane >> 2, gc = lane & 3;
    const int bm = blockIdx.y, bn = blockIdx.x;

    const bf16* Ag0 = A  + (size_t)bm * 128 * lda;
    const bf16* Bg0 = Bt + (size_t)bn * 256 * K;
    const int NC = K / KC;

    float acc[4][8][4];
    #pragma unroll
    for (int mt = 0; mt < 4; mt++)
        #pragma unroll
        for (int nt = 0; nt < 8; nt++)
            #pragma unroll
            for (int i = 0; i < 4; i++) acc[mt][nt][i] = 0.f;

    uint32_t aAddr[4], bAddr[4];
    {
        int arow = (lane & 15);
        int acol = (lane >> 4) * 8;
        #pragma unroll
        for (int mt = 0; mt < 4; mt++) {
            int r = wr*64 + mt*16 + arow;
            aAddr[mt] = sbase + (uint32_t)(r * LDSB + acol) * 2;
        }
        int brow = ((lane >> 4) * 8) + (lane & 7);
        int bcol = ((lane >> 3) & 1) * 8;
        #pragma unroll
        for (int p = 0; p < 4; p++) {
            int r = wn*64 + p*16 + brow;
            bAddr[p] = sbase + (uint32_t)(TILE_A_BF + r * LDSB + bcol) * 2;
        }
    }

    auto load_chunk = [&](int kc, int s) {
        bf16* As = smem + s * STAGE_BF;
        bf16* Bs = As + TILE_A_BF;
        const bf16* Agc = Ag0 + kc * KC;
        const bf16* Bgc = Bg0 + kc * KC;
        #pragma unroll
        for (int j = 0; j < 4; j++) {
            int slot = tid + 256 * j;
            int row  = slot >> 3, c8 = slot & 7;
            uint32_t da = smem_u32(As + row * LDSB + c8 * 8);
            CP_ASYNC16(da, Agc + (size_t)row * lda + c8 * 8);
        }
        #pragma unroll
        for (int j = 0; j < 8; j++) {
            int slot = tid + 256 * j;
            int row  = slot >> 3, c8 = slot & 7;
            uint32_t db = smem_u32(Bs + row * LDSB + c8 * 8);
            CP_ASYNC16(db, Bgc + (size_t)row * K + c8 * 8);
        }
        CP_COMMIT();
    };

    uint32_t fa[2][4][4], fb[2][4][4];
    auto ldsm_all = [&](int buf, uint32_t ko) {
        #pragma unroll
        for (int mt = 0; mt < 4; mt++)
            LDSM_X4(fa[buf][mt][0], fa[buf][mt][1], fa[buf][mt][2], fa[buf][mt][3],
                    aAddr[mt] + ko);
        #pragma unroll
        for (int p = 0; p < 4; p++)
            LDSM_X4(fb[buf][p][0], fb[buf][p][1], fb[buf][p][2], fb[buf][p][3],
                    bAddr[p] + ko);
    };
    auto mma_all = [&](int buf) {
        #pragma unroll
        for (int mt = 0; mt < 4; mt++)
            #pragma unroll
            for (int nt = 0; nt < 8; nt++)
                mma_bf16(acc[mt][nt], fa[buf][mt], &fb[buf][nt >> 1][(nt & 1) * 2]);
    };

    load_chunk(0, 0);
    if (NC > 1) { load_chunk(1, 1); CP_WAIT1(); } else { CP_WAIT0(); }
    __syncthreads();
    ldsm_all(0, 0);

    int stg = 0;
    for (int i = 0; i < NC; i++) {
        if (i + 2 < NC) load_chunk(i + 2, (stg + 2) % NSTG);
        const uint32_t soff = stg * STAGE_BYTES;
        #pragma unroll
        for (int kk = 0; kk < 3; kk++) {
            ldsm_all((kk + 1) & 1, soff + (kk + 1) * 32);
            mma_all(kk & 1);
        }
        if (i + 1 < NC) {
            if (i + 2 < NC) CP_WAIT1(); else CP_WAIT0();
            __syncthreads();
            ldsm_all(0, ((stg + 1) % NSTG) * STAGE_BYTES);
            mma_all(1);
        } else {
            mma_all(1);
        }
        stg = (stg + 1) % NSTG;
    }
    __syncthreads();

    const int cbase = bn * 256 + wn * 64;
    if (!EPILN) {
        #pragma unroll
        for (int mt = 0; mt < 4; mt++) {
            #pragma unroll
            for (int rr = 0; rr < 2; rr++) {
                int r = bm * 128 + wr * 64 + mt * 16 + gr + rr * 8;
                const float* rrow = RESID ? (resid + (size_t)r * ldc + cbase) : nullptr;
                #pragma unroll
                for (int nt = 0; nt < 8; nt++) {
                    int ci = nt * 8 + 2 * gc;
                    float v0 = acc[mt][nt][rr*2 + 0] + bias[cbase + ci];
                    float v1 = acc[mt][nt][rr*2 + 1] + bias[cbase + ci + 1];
                    if (RESID) {
                        float2 rv = *(const float2*)(rrow + ci);
                        v0 += rv.x; v1 += rv.y;
                    }
                    if (ACT == 1) { v0 = fmaxf(v0, 0.f); v1 = fmaxf(v1, 0.f); }
                    if (OBF) {
                        bf16* crow = (bf16*)Cv + (size_t)r * ldc + cbase;
                        __nv_bfloat162 bv;
                        bv.x = __float2bfloat16_rn(v0);
                        bv.y = __float2bfloat16_rn(v1);
                        *(__nv_bfloat162*)(crow + ci) = bv;
                    } else {
                        float* crow = (float*)Cv + (size_t)r * ldc + cbase;
                        *(float2*)(crow + ci) = make_float2(v0, v1);
                    }
                }
            }
        }
    } else {
        float* red = (float*)smem;
        #pragma unroll
        for (int mt = 0; mt < 4; mt++) {
            #pragma unroll
            for (int rr = 0; rr < 2; rr++) {
                int rl = wr * 64 + mt * 16 + rr * 8 + gr;
                int r  = bm * 128 + rl;
                const float* rrow = resid + (size_t)r * ldc + cbase;
                float* crow = (float*)Cv + (size_t)r * ldc + cbase;
                float s = 0.f, sq = 0.f;
                #pragma unroll
                for (int nt = 0; nt < 8; nt++) {
                    int ci = nt * 8 + 2 * gc;
                    float2 rv = *(const float2*)(rrow + ci);
                    float v0 = acc[mt][nt][rr*2 + 0] + bias[cbase + ci]     + rv.x;
                    float v1 = acc[mt][nt][rr*2 + 1] + bias[cbase + ci + 1] + rv.y;
                    acc[mt][nt][rr*2 + 0] = v0;
                    acc[mt][nt][rr*2 + 1] = v1;
                    *(float2*)(crow + ci) = make_float2(v0, v1);
                    s += v0 + v1; sq += v0*v0 + v1*v1;
                }
                s  += __shfl_xor_sync(0xffffffffu, s, 1);
                sq += __shfl_xor_sync(0xffffffffu, sq, 1);
                s  += __shfl_xor_sync(0xffffffffu, s, 2);
                sq += __shfl_xor_sync(0xffffffffu, sq, 2);
                if (gc == 0) {
                    red[rl * 8 + wn * 2 + 0] = s;
                    red[rl * 8 + wn * 2 + 1] = sq;
                }
            }
        }
        __syncthreads();
        #pragma unroll
        for (int mt = 0; mt < 4; mt++) {
            #pragma unroll
            for (int rr = 0; rr < 2; rr++) {
                int rl = wr * 64 + mt * 16 + rr * 8 + gr;
                int r  = bm * 128 + rl;
                float s  = red[rl*8+0] + red[rl*8+2] + red[rl*8+4] + red[rl*8+6];
                float sq = red[rl*8+1] + red[rl*8+3] + red[rl*8+5] + red[rl*8+7];
                float mean = s * (1.0f/Dn);
                float var  = sq * (1.0f/Dn) - mean*mean;
                float rstd = rsqrtf(var + 1e-5f);
                bf16* hrow = hout + (size_t)r * Dn + cbase;
                #pragma unroll
                for (int nt = 0; nt < 8; nt++) {
                    int ci = nt * 8 + 2 * gc;
                    float g0 = lng[cbase + ci], g1 = lng[cbase + ci + 1];
                    float be0 = lnb[cbase + ci], be1 = lnb[cbase + ci + 1];
                    float u0 = (acc[mt][nt][rr*2+0] - mean) * rstd * g0 + be0;
                    float u1 = (acc[mt][nt][rr*2+1] - mean) * rstd * g1 + be1;
                    __nv_bfloat162 bv;
                    bv.x = __float2bfloat16_rn(u0);
                    bv.y = __float2bfloat16_rn(u1);
                    *(__nv_bfloat162*)(hrow + ci) = bv;
                }
            }
        }
    }
}

// ======== SMALL kernel v2: 128x128 tile, 256 thr, 2 CTAs/SM (16 warps/SM) ========
// warp grid 4x2 (M x N), warp tile 32x64; single-buffered frags (cross-warp latency hiding).
static constexpr int TILE_A_SM = 128 * LDSB;               // 9216
static constexpr int TILE_B_SM = 128 * LDSB;               // 9216
static constexpr int STAGE_SM  = TILE_A_SM + TILE_B_SM;    // 18432 bf16
static constexpr int STAGE_SM_BYTES = STAGE_SM * 2;        // 36864
static constexpr int SM_SMEM_BYTES = NSTG * STAGE_SM_BYTES; // 110592

template<int ACT, bool RESID, bool OBF>
__global__ __launch_bounds__(256, 2)
void gemm_tc_sm(const bf16* __restrict__ A, int lda,
                const bf16* __restrict__ Bt,
                const float* __restrict__ bias,
                const float* __restrict__ resid,
                void* __restrict__ Cv, int ldc, int K) {
    extern __shared__ bf16 smem[];
    const uint32_t sbase = smem_u32(smem);
    const int tid = threadIdx.x;
    const int wid = tid >> 5, lane = tid & 31;
    const int wr = wid >> 1, wn = wid & 1;      // 4x2 warp grid, 32x64 warp tiles
    const int gr = lane >> 2, gc = lane & 3;
    const int bm = blockIdx.y, bn = blockIdx.x;

    const bf16* Ag0 = A  + (size_t)bm * 128 * lda;
    const bf16* Bg0 = Bt + (size_t)bn * 128 * K;
    const int NC = K / KC;

    float acc[2][8][4];
    #pragma unroll
    for (int mt = 0; mt < 2; mt++)
        #pragma unroll
        for (int nt = 0; nt < 8; nt++)
            #pragma unroll
            for (int i = 0; i < 4; i++) acc[mt][nt][i] = 0.f;

    uint32_t aAddr[2], bAddr[4];
    {
        int arow = (lane & 15);
        int acol = (lane >> 4) * 8;
        #pragma unroll
        for (int mt = 0; mt < 2; mt++) {
            int r = wr*32 + mt*16 + arow;
            aAddr[mt] = sbase + (uint32_t)(r * LDSB + acol) * 2;
        }
        int brow = ((lane >> 4) * 8) + (lane & 7);
        int bcol = ((lane >> 3) & 1) * 8;
        #pragma unroll
        for (int p = 0; p < 4; p++) {
            int r = wn*64 + p*16 + brow;
            bAddr[p] = sbase + (uint32_t)(TILE_A_SM + r * LDSB + bcol) * 2;
        }
    }

    auto load_chunk = [&](int kc, int s) {
        bf16* As = smem + s * STAGE_SM;
        bf16* Bs = As + TILE_A_SM;
        const bf16* Agc = Ag0 + kc * KC;
        const bf16* Bgc = Bg0 + kc * KC;
        // A: 128x64 = 1024 slots / 256 thr = 4 each; B same
        #pragma unroll
        for (int j = 0; j < 4; j++) {
            int slot = tid + 256 * j;
            int row  = slot >> 3, c8 = slot & 7;
            uint32_t da = smem_u32(As + row * LDSB + c8 * 8);
            CP_ASYNC16(da, Agc + (size_t)row * lda + c8 * 8);
            uint32_t db = smem_u32(Bs + row * LDSB + c8 * 8);
            CP_ASYNC16(db, Bgc + (size_t)row * K + c8 * 8);
        }
        CP_COMMIT();
    };

    uint32_t fa[2][4], fb[4][4];
    auto step = [&](uint32_t ko) {
        #pragma unroll
        for (int mt = 0; mt < 2; mt++)
            LDSM_X4(fa[mt][0], fa[mt][1], fa[mt][2], fa[mt][3], aAddr[mt] + ko);
        #pragma unroll
        for (int p = 0; p < 4; p++)
            LDSM_X4(fb[p][0], fb[p][1], fb[p][2], fb[p][3], bAddr[p] + ko);
        #pragma unroll
        for (int mt = 0; mt < 2; mt++)
            #pragma unroll
            for (int nt = 0; nt < 8; nt++)
                mma_bf16(acc[mt][nt], fa[mt], &fb[nt >> 1][(nt & 1) * 2]);
    };

    load_chunk(0, 0);
    if (NC > 1) load_chunk(1, 1);

    int stg = 0;
    for (int i = 0; i < NC; i++) {
        if (i + 1 < NC) CP_WAIT1(); else CP_WAIT0();
        __syncthreads();
        if (i + 2 < NC) load_chunk(i + 2, (stg + 2) % NSTG);
        const uint32_t soff = stg * STAGE_SM_BYTES;
        #pragma unroll
        for (int kk = 0; kk < 4; kk++)
            step(soff + kk * 32);
        stg = (stg + 1) % NSTG;
    }

    // ---- epilogue ----
    const int cbase = bn * 128 + wn * 64;
    #pragma unroll
    for (int mt = 0; mt < 2; mt++) {
        #pragma unroll
        for (int rr = 0; rr < 2; rr++) {
            int r = bm * 128 + wr * 32 + mt * 16 + gr + rr * 8;
            const float* rrow = RESID ? (resid + (size_t)r * ldc + cbase) : nullptr;
            #pragma unroll
            for (int nt = 0; nt < 8; nt++) {
                int ci = nt * 8 + 2 * gc;
                float v0 = acc[mt][nt][rr*2 + 0] + bias[cbase + ci];
                float v1 = acc[mt][nt][rr*2 + 1] + bias[cbase + ci + 1];
                if (RESID) {
                    float2 rv = *(const float2*)(rrow + ci);
                    v0 += rv.x; v1 += rv.y;
                }
                if (ACT == 1) { v0 = fmaxf(v0, 0.f); v1 = fmaxf(v1, 0.f); }
                if (OBF) {
                    bf16* crow = (bf16*)Cv + (size_t)r * ldc + cbase;
                    __nv_bfloat162 bv;
                    bv.x = __float2bfloat16_rn(v0);
                    bv.y = __float2bfloat16_rn(v1);
                    *(__nv_bfloat162*)(crow + ci) = bv;
                } else {
                    float* crow = (float*)Cv + (size_t)r * ldc + cbase;
                    *(float2*)(crow + ci) = make_float2(v0, v1);
                }
            }
        }
    }
}

// ---------------- fused build_x + first LN: 1 warp per row ----------------
__global__ void build_ln_kernel(const float* __restrict__ term,
                                const float* __restrict__ pred,
                                const float* __restrict__ gam,
                                const float* __restrict__ bet,
                                float* __restrict__ x, bf16* __restrict__ h) {
    int warp = (blockIdx.x * blockDim.x + threadIdx.x) >> 5;
    int lane = threadIdx.x & 31;
    if (warp >= MROWS) return;
    int s3 = warp % 3;
    int n = warp / 3;
    int t = n / Bn;
    int b = n % Bn;
    const int srcT[3][3] = {{1,2,0},{0,2,1},{1,0,2}};
    const int srcP[3][3] = {{0,2,-1},{0,1,-1},{1,2,-1}};
    const float sgn[3][3] = {{-1.f,-1.f,0.f},{1.f,-1.f,0.f},{1.f,1.f,0.f}};
    int tt = srcT[t][s3];
    int pp = srcP[t][s3];
    float sg = sgn[t][s3];
    const float* trow = term + ((size_t)tt*Bn + b)*Dn + lane*8;
    float4 a0 = *(const float4*)(trow);
    float4 a1 = *(const float4*)(trow + 4);
    float vals[8] = {a0.x,a0.y,a0.z,a0.w,a1.x,a1.y,a1.z,a1.w};
    if (pp >= 0) {
        const float* prow = pred + ((size_t)pp*Bn + b)*Dn + lane*8;
        float4 p0 = *(const float4*)(prow);
        float4 p1 = *(const float4*)(prow + 4);
        float pv[8] = {p0.x,p0.y,p0.z,p0.w,p1.x,p1.y,p1.z,p1.w};
        #pragma unroll
        for (int i = 0; i < 8; i++) vals[i] += sg * pv[i];
    }
    float* xrow = x + (size_t)warp * Dn + lane*8;
    *(float4*)(xrow)     = make_float4(vals[0],vals[1],vals[2],vals[3]);
    *(float4*)(xrow + 4) = make_float4(vals[4],vals[5],vals[6],vals[7]);
    float s = 0.f, sq = 0.f;
    #pragma unroll
    for (int i = 0; i < 8; i++) { s += vals[i]; sq += vals[i]*vals[i]; }
    #pragma unroll
    for (int o = 16; o > 0; o >>= 1) {
        s  += __shfl_xor_sync(0xffffffffu, s,  o);
        sq += __shfl_xor_sync(0xffffffffu, sq, o);
    }
    float mean = s * (1.0f/Dn);
    float var  = sq * (1.0f/Dn) - mean*mean;
    float rstd = rsqrtf(var + 1e-5f);
    float4 g0 = *(const float4*)(gam + lane*8);
    float4 g1 = *(const float4*)(gam + lane*8 + 4);
    float4 b0 = *(const float4*)(bet + lane*8);
    float4 b1 = *(const float4*)(bet + lane*8 + 4);
    float gs[8] = {g0.x,g0.y,g0.z,g0.w,g1.x,g1.y,g1.z,g1.w};
    float bs[8] = {b0.x,b0.y,b0.z,b0.w,b1.x,b1.y,b1.z,b1.w};
    __nv_bfloat162 ov[4];
    #pragma unroll
    for (int i = 0; i < 4; i++) {
        float u0 = (vals[2*i]  -mean)*rstd*gs[2*i]   + bs[2*i];
        float u1 = (vals[2*i+1]-mean)*rstd*gs[2*i+1] + bs[2*i+1];
        ov[i].x = __float2bfloat16_rn(u0);
        ov[i].y = __float2bfloat16_rn(u1);
    }
    *(uint4*)(h + (size_t)warp * Dn + lane*8) = *(uint4*)ov;
}

// ---------------- standalone layernorm: 1 warp per row (fp32 in, bf16 out) ----------------
__global__ void ln_kernel(const float* __restrict__ x,
                          const float* __restrict__ gam,
                          const float* __restrict__ bet,
                          bf16* __restrict__ out) {
    int warp = (blockIdx.x * blockDim.x + threadIdx.x) >> 5;
    int lane = threadIdx.x & 31;
    if (warp >= MROWS) return;
    const float* row = x + (size_t)warp * Dn;
    float4 a0 = *(const float4*)(row + lane*8);
    float4 a1 = *(const float4*)(row + lane*8 + 4);
    float vals[8] = {a0.x,a0.y,a0.z,a0.w,a1.x,a1.y,a1.z,a1.w};
    float s = 0.f, sq = 0.f;
    #pragma unroll
    for (int i = 0; i < 8; i++) { s += vals[i]; sq += vals[i]*vals[i]; }
    #pragma unroll
    for (int o = 16; o > 0; o >>= 1) {
        s  += __shfl_xor_sync(0xffffffffu, s,  o);
        sq += __shfl_xor_sync(0xffffffffu, sq, o);
    }
    float mean = s * (1.0f/Dn);
    float var  = sq * (1.0f/Dn) - mean*mean;
    float rstd = rsqrtf(var + 1e-5f);
    float4 g0 = *(const float4*)(gam + lane*8);
    float4 g1 = *(const float4*)(gam + lane*8 + 4);
    float4 b0 = *(const float4*)(bet + lane*8);
    float4 b1 = *(const float4*)(bet + lane*8 + 4);
    float gs[8] = {g0.x,g0.y,g0.z,g0.w,g1.x,g1.y,g1.z,g1.w};
    float bs[8] = {b0.x,b0.y,b0.z,b0.w,b1.x,b1.y,b1.z,b1.w};
    __nv_bfloat162 ov[4];
    #pragma unroll
    for (int i = 0; i < 4; i++) {
        float u0 = (vals[2*i]  -mean)*rstd*gs[2*i]   + bs[2*i];
        float u1 = (vals[2*i+1]-mean)*rstd*gs[2*i+1] + bs[2*i+1];
        ov[i].x = __float2bfloat16_rn(u0);
        ov[i].y = __float2bfloat16_rn(u1);
    }
    *(uint4*)(out + (size_t)warp * Dn + lane*8) = *(uint4*)ov;
}

// ---------------- attention on fused qkv buffer (bf16): 1 warp per (n, head) ----------------
__global__ void attn_kernel(const bf16* __restrict__ qkv, bf16* __restrict__ o) {
    int widx = (blockIdx.x * blockDim.x + threadIdx.x) >> 5;
    int lane = threadIdx.x & 31;
    if (widx >= NG * Hn) return;
    int n = widx >> 3;
    int h = widx & 7;
    size_t rb = (size_t)n * 3 * (3*Dn) + h*DHn + lane;
    float qs[3], ks[3], vs[3];
    #pragma unroll
    for (int s = 0; s < 3; s++) {
        qs[s] = __bfloat162float(qkv[rb + (size_t)s*(3*Dn)]);
        ks[s] = __bfloat162float(qkv[rb + (size_t)s*(3*Dn) + Dn]);
        vs[s] = __bfloat162float(qkv[rb + (size_t)s*(3*Dn) + 2*Dn]);
    }
    float sc[3][3];
    #pragma unroll
    for (int s = 0; s < 3; s++)
        #pragma unroll
        for (int t = 0; t < 3; t++) {
            float p = qs[s]*ks[t];
            #pragma unroll
            for (int off = 16; off > 0; off >>= 1)
                p += __shfl_xor_sync(0xffffffffu, p, off);
            sc[s][t] = p * SCALE_F;
        }
    #pragma unroll
    for (int s = 0; s < 3; s++) {
        float m = fmaxf(sc[s][0], fmaxf(sc[s][1], sc[s][2]));
        float e0 = __expf(sc[s][0]-m);
        float e1 = __expf(sc[s][1]-m);
        float e2 = __expf(sc[s][2]-m);
        float inv = 1.0f/(e0+e1+e2);
        float os = (e0*vs[0] + e1*vs[1] + e2*vs[2]) * inv;
        o[(size_t)(n*3+s)*Dn + h*DHn + lane] = __float2bfloat16_rn(os);
    }
}

// ---------------- one-shot transpose+convert of all weights (both layers) ----------------
__global__ void transpose_all(const float* __restrict__ Wq, const float* __restrict__ Wk,
                              const float* __restrict__ Wv, const float* __restrict__ Wo,
                              const float* __restrict__ W1, const float* __restrict__ W2,
                              bf16* __restrict__ wt) {
    __shared__ float t[32][33];
    int bid = blockIdx.x;
    int l = bid / 768;
    int tt = bid % 768;
    const float* in; bf16* out; int N, n0, k0, outld;
    if (tt < 192) {
        int which = tt / 64; int q = tt % 64;
        const float* Ws[3] = {Wq, Wk, Wv};
        in = Ws[which] + (size_t)l*Dn*Dn;
        out = wt + (size_t)l*WT_LAYER + which*Dn*Dn;
        N = Dn; outld = Dn;
        n0 = (q & 7) * 32; k0 = (q >> 3) * 32;
    } else if (tt < 256) {
        int q = tt - 192;
        in = Wo + (size_t)l*Dn*Dn;
        out = wt + (size_t)l*WT_LAYER + 196608;
        N = Dn; outld = Dn;
        n0 = (q & 7) * 32; k0 = (q >> 3) * 32;
    } else if (tt < 512) {
        int q = tt - 256;
        in = W1 + (size_t)l*Dn*FFn;
        out = wt + (size_t)l*WT_LAYER + 262144;
        N = FFn; outld = Dn;
        n0 = (q & 31) * 32; k0 = (q >> 5) * 32;
    } else {
        int q = tt - 512;
        in = W2 + (size_t)l*FFn*Dn;
        out = wt + (size_t)l*WT_LAYER + 524288;
        N = Dn; outld = FFn;
        n0 = (q & 7) * 32; k0 = (q >> 3) * 32;
    }
    int tx = threadIdx.x, ty = threadIdx.y;   // 32 x 8
    #pragma unroll
    for (int i = ty; i < 32; i += 8)
        t[i][tx] = in[(size_t)(k0+i)*N + n0+tx];
    __syncthreads();
    #pragma unroll
    for (int i = ty; i < 32; i += 8)
        out[(size_t)(n0+i)*outld + k0+tx] = __float2bfloat16_rn(t[tx][i]);
}

__global__ void concat_bias_kernel(const float* __restrict__ bq, const float* __restrict__ bk,
                                   const float* __restrict__ bv, float* __restrict__ out) {
    int i = blockIdx.x*blockDim.x + threadIdx.x;
    if (i >= 2*3*Dn) return;
    int l = i / (3*Dn);
    int j = i % (3*Dn);
    float v;
    if (j < Dn)        v = bq[l*Dn + j];
    else if (j < 2*Dn) v = bk[l*Dn + j-Dn];
    else               v = bv[l*Dn + j-2*Dn];
    out[i] = v;
}

// ---------------- fused final LN + mean-pool: 1 warp per group ----------------
__global__ void ln_mean_kernel(const float* __restrict__ x,
                               const float* __restrict__ gam,
                               const float* __restrict__ bet,
                               float* __restrict__ out) {
    int warp = (blockIdx.x * blockDim.x + threadIdx.x) >> 5;
    int lane = threadIdx.x & 31;
    if (warp >= NG) return;
    float4 g0 = *(const float4*)(gam + lane*8);
    float4 g1 = *(const float4*)(gam + lane*8 + 4);
    float4 b0 = *(const float4*)(bet + lane*8);
    float4 b1 = *(const float4*)(bet + lane*8 + 4);
    float gs[8] = {g0.x,g0.y,g0.z,g0.w,g1.x,g1.y,g1.z,g1.w};
    float bs[8] = {b0.x,b0.y,b0.z,b0.w,b1.x,b1.y,b1.z,b1.w};
    float avg[8] = {0,0,0,0,0,0,0,0};
    #pragma unroll
    for (int s3 = 0; s3 < 3; s3++) {
        const float* row = x + ((size_t)warp*3 + s3) * Dn;
        float4 a0 = *(const float4*)(row + lane*8);
        float4 a1 = *(const float4*)(row + lane*8 + 4);
        float vals[8] = {a0.x,a0.y,a0.z,a0.w,a1.x,a1.y,a1.z,a1.w};
        float s = 0.f, sq = 0.f;
        #pragma unroll
        for (int i = 0; i < 8; i++) { s += vals[i]; sq += vals[i]*vals[i]; }
        #pragma unroll
        for (int o = 16; o > 0; o >>= 1) {
            s  += __shfl_xor_sync(0xffffffffu, s,  o);
            sq += __shfl_xor_sync(0xffffffffu, sq, o);
        }
        float mean = s * (1.0f/Dn);
        float var  = sq * (1.0f/Dn) - mean*mean;
        float rstd = rsqrtf(var + 1e-5f);
        #pragma unroll
        for (int i = 0; i < 8; i++)
            avg[i] += ((vals[i]-mean)*rstd*gs[i] + bs[i]) * (1.0f/3.0f);
    }
    float* orow = out + (size_t)warp * Dn;
    *(float4*)(orow + lane*8)     = make_float4(avg[0],avg[1],avg[2],avg[3]);
    *(float4*)(orow + lane*8 + 4) = make_float4(avg[4],avg[5],avg[6],avg[7]);
}

// ---------------- host ----------------
extern "C" void kernel_launch(void* const* d_in, const int* in_sizes, int n_in,
                              void* d_out, int out_size) {
    const float* term  = (const float*)d_in[0];
    const float* pred  = (const float*)d_in[1];
    const float* Wq    = (const float*)d_in[2];
    const float* Wk    = (const float*)d_in[3];
    const float* Wv    = (const float*)d_in[4];
    const float* Wo    = (const float*)d_in[5];
    const float* bq    = (const float*)d_in[6];
    const float* bk    = (const float*)d_in[7];
    const float* bv    = (const float*)d_in[8];
    const float* bo    = (const float*)d_in[9];
    const float* ln1g  = (const float*)d_in[10];
    const float* ln1b  = (const float*)d_in[11];
    const float* ln2g  = (const float*)d_in[12];
    const float* ln2b  = (const float*)d_in[13];
    const float* W1    = (const float*)d_in[14];
    const float* b1    = (const float*)d_in[15];
    const float* W2    = (const float*)d_in[16];
    const float* b2    = (const float*)d_in[17];
    const float* lnfg  = (const float*)d_in[18];
    const float* lnfb  = (const float*)d_in[19];
    float* out = (float*)d_out;

    float *x, *bqkv;
    bf16 *h, *qkv, *o, *f, *wt;
    cudaGetSymbolAddress((void**)&x,   g_x);
    cudaGetSymbolAddress((void**)&h,   g_h);
    cudaGetSymbolAddress((void**)&qkv, g_qkv);
    cudaGetSymbolAddress((void**)&o,   g_o);
    cudaGetSymbolAddress((void**)&f,   g_f);
    cudaGetSymbolAddress((void**)&wt,  g_wt);
    cudaGetSymbolAddress((void**)&bqkv,g_bqkv);

    cudaFuncSetAttribute(gemm_tc<0,true ,false,true >, cudaFuncAttributeMaxDynamicSharedMemorySize, GEMM_SMEM_BYTES);
    cudaFuncSetAttribute(gemm_tc_sm<0,false,true >, cudaFuncAttributeMaxDynamicSharedMemorySize, SM_SMEM_BYTES);
    cudaFuncSetAttribute(gemm_tc_sm<1,false,true >, cudaFuncAttributeMaxDynamicSharedMemorySize, SM_SMEM_BYTES);
    cudaFuncSetAttribute(gemm_tc_sm<0,true ,false>, cudaFuncAttributeMaxDynamicSharedMemorySize, SM_SMEM_BYTES);

    // weight prep + fused build_x + LN1(layer0)
    transpose_all<<<2*768, dim3(32,8)>>>(Wq, Wk, Wv, Wo, W1, W2, wt);
    concat_bias_kernel<<<6, 256>>>(bq, bk, bv, bqkv);
    build_ln_kernel<<<MROWS/8, 256>>>(term, pred, ln1g, ln1b, x, h);

    const int MB  = MROWS / 128;  // 1152
    for (int l = 0; l < NLn; l++) {
        const bf16* wl = wt + (size_t)l*WT_LAYER;

        // fused QKV GEMM (small v2, 2 CTAs/SM, 16 warps/SM): [MROWS,256] @ [256,768]
        gemm_tc_sm<0,false,true><<<dim3(6, MB), 256, SM_SMEM_BYTES>>>(
            h, Dn, wl, bqkv + l*3*Dn, nullptr, qkv, 3*Dn, Dn);

        // attention
        attn_kernel<<<NG*Hn/8, 256>>>(qkv, o);

        // output projection + residual -> x fp32, fused LN2 -> h bf16 (large EPILN)
        gemm_tc<0,true,false,true><<<dim3(1, MB), 256, GEMM_SMEM_BYTES>>>(
            o, Dn, wl + 196608, bo + l*Dn, x, x, Dn, Dn,
            ln2g + l*Dn, ln2b + l*Dn, h);

        // FFN up (relu, small v2): [MROWS,256] @ [256,1024]
        gemm_tc_sm<1,false,true><<<dim3(8, MB), 256, SM_SMEM_BYTES>>>(
            h, Dn, wl + 262144, b1 + l*FFn, nullptr, f, FFn, Dn);

        // FFN down + residual -> x fp32 (small v2)
        gemm_tc_sm<0,true,false><<<dim3(2, MB), 256, SM_SMEM_BYTES>>>(
            f, FFn, wl + 524288, b2 + l*Dn, x, x, Dn, FFn);

        // LN1 of next layer (standalone)
        if (l + 1 < NLn)
            ln_kernel<<<MROWS/8, 256>>>(x, ln1g + (l+1)*Dn, ln1b + (l+1)*Dn, h);
    }

    // fused final LN + mean pool
    ln_mean_kernel<<<NG/8, 256>>>(x, lnfg, lnfb, out);
    (void)in_sizes; (void)n_in; (void)out_size;
}

// round 15
// speedup vs baseline: 1.0575x; 1.0575x over previous
#include <cuda_runtime.h>
#include <cuda_bf16.h>
#include <cstdint>
#include <math.h>

// Problem constants
#define Tn   3
#define Bn   16384
#define Dn   256
#define Hn   8
#define DHn  32
#define NLn  2
#define FFn  1024
#define NG   (Tn*Bn)        // 49152 row-groups
#define MROWS (NG*3)        // 147456 total rows
#define SCALE_F 0.17677669529663687f   // 1/sqrt(32)

typedef __nv_bfloat16 bf16;

// ---------------- device scratch (allocation-free) ----------------
__device__ float g_x[MROWS*Dn];                 // residual stream (fp32)
__device__ bf16  g_h[MROWS*Dn];                 // LN output (bf16)
__device__ bf16  g_qkv[(size_t)MROWS*3*Dn];     // fused QKV output (bf16)
__device__ bf16  g_o[MROWS*Dn];                 // attention output (bf16)
__device__ bf16  g_f[(size_t)MROWS*FFn];        // FFN intermediate (bf16)
#define WT_LAYER 786432
__device__ bf16  g_wt[2*WT_LAYER];
__device__ float g_bqkv[2*3*Dn];                // concatenated qkv bias, both layers

// =================== helpers ===================
__device__ __forceinline__ uint32_t smem_u32(const void* p) {
    uint32_t a;
    asm("{ .reg .u64 t; cvta.to.shared.u64 t, %1; cvt.u32.u64 %0, t; }" : "=r"(a) : "l"(p));
    return a;
}
#define CP_ASYNC16(dst, src) \
    asm volatile("cp.async.cg.shared.global [%0], [%1], 16;" :: "r"(dst), "l"(src) : "memory")
#define CP_COMMIT() asm volatile("cp.async.commit_group;" ::: "memory")
#define CP_WAIT0()  asm volatile("cp.async.wait_group 0;" ::: "memory")
#define CP_WAIT1()  asm volatile("cp.async.wait_group 1;" ::: "memory")

#define LDSM_X4(r0, r1, r2, r3, addr) \
    asm volatile("ldmatrix.sync.aligned.m8n8.x4.shared.b16 {%0,%1,%2,%3}, [%4];" \
        : "=r"(r0), "=r"(r1), "=r"(r2), "=r"(r3) : "r"(addr))

// mma.sync m16n8k16 bf16
__device__ __forceinline__ void mma_bf16(float* c, const uint32_t* a, const uint32_t* b) {
    asm volatile(
        "mma.sync.aligned.m16n8k16.row.col.f32.bf16.bf16.f32 "
        "{%0,%1,%2,%3}, {%4,%5,%6,%7}, {%8,%9}, {%0,%1,%2,%3};"
        : "+f"(c[0]), "+f"(c[1]), "+f"(c[2]), "+f"(c[3])
        : "r"(a[0]), "r"(a[1]), "r"(a[2]), "r"(a[3]), "r"(b[0]), "r"(b[1]));
}

#define KC   64
#define LDSB 72

// ======== LARGE kernel: 128x256 tile, 256 thr, 1 CTA/SM — used for EPILN proj ========
#define NSTG 3
static constexpr int TILE_A_BF = 128 * LDSB;              // 9216
static constexpr int TILE_B_BF = 256 * LDSB;              // 18432
static constexpr int STAGE_BF  = TILE_A_BF + TILE_B_BF;   // 27648
static constexpr int STAGE_BYTES = STAGE_BF * 2;          // 55296
static constexpr int GEMM_SMEM_BYTES = NSTG * STAGE_BYTES; // 165888

template<int ACT, bool RESID, bool OBF, bool EPILN>
__global__ __launch_bounds__(256)
void gemm_tc(const bf16* __restrict__ A, int lda,
             const bf16* __restrict__ Bt,
             const float* __restrict__ bias,
             const float* __restrict__ resid,
             void* __restrict__ Cv, int ldc, int K,
             const float* __restrict__ lng, const float* __restrict__ lnb,
             bf16* __restrict__ hout) {
    extern __shared__ bf16 smem[];
    const uint32_t sbase = smem_u32(smem);
    const int tid = threadIdx.x;
    const int wid = tid >> 5, lane = tid & 31;
    const int wr = wid >> 2, wn = wid & 3;      // 2x4 warp grid (M x N)
    const int gr = lane >> 2, gc = lane & 3;
    const int bm = blockIdx.y, bn = blockIdx.x;

    const bf16* Ag0 = A  + (size_t)bm * 128 * lda;
    const bf16* Bg0 = Bt + (size_t)bn * 256 * K;
    const int NC = K / KC;

    float acc[4][8][4];
    #pragma unroll
    for (int mt = 0; mt < 4; mt++)
        #pragma unroll
        for (int nt = 0; nt < 8; nt++)
            #pragma unroll
            for (int i = 0; i < 4; i++) acc[mt][nt][i] = 0.f;

    uint32_t aAddr[4], bAddr[4];
    {
        int arow = (lane & 15);
        int acol = (lane >> 4) * 8;
        #pragma unroll
        for (int mt = 0; mt < 4; mt++) {
            int r = wr*64 + mt*16 + arow;
            aAddr[mt] = sbase + (uint32_t)(r * LDSB + acol) * 2;
        }
        int brow = ((lane >> 4) * 8) + (lane & 7);
        int bcol = ((lane >> 3) & 1) * 8;
        #pragma unroll
        for (int p = 0; p < 4; p++) {
            int r = wn*64 + p*16 + brow;
            bAddr[p] = sbase + (uint32_t)(TILE_A_BF + r * LDSB + bcol) * 2;
        }
    }

    auto load_chunk = [&](int kc, int s) {
        bf16* As = smem + s * STAGE_BF;
        bf16* Bs = As + TILE_A_BF;
        const bf16* Agc = Ag0 + kc * KC;
        const bf16* Bgc = Bg0 + kc * KC;
        #pragma unroll
        for (int j = 0; j < 4; j++) {
            int slot = tid + 256 * j;
            int row  = slot >> 3, c8 = slot & 7;
            uint32_t da = smem_u32(As + row * LDSB + c8 * 8);
            CP_ASYNC16(da, Agc + (size_t)row * lda + c8 * 8);
        }
        #pragma unroll
        for (int j = 0; j < 8; j++) {
            int slot = tid + 256 * j;
            int row  = slot >> 3, c8 = slot & 7;
            uint32_t db = smem_u32(Bs + row * LDSB + c8 * 8);
            CP_ASYNC16(db, Bgc + (size_t)row * K + c8 * 8);
        }
        CP_COMMIT();
    };

    uint32_t fa[2][4][4], fb[2][4][4];
    auto ldsm_all = [&](int buf, uint32_t ko) {
        #pragma unroll
        for (int mt = 0; mt < 4; mt++)
            LDSM_X4(fa[buf][mt][0], fa[buf][mt][1], fa[buf][mt][2], fa[buf][mt][3],
                    aAddr[mt] + ko);
        #pragma unroll
        for (int p = 0; p < 4; p++)
            LDSM_X4(fb[buf][p][0], fb[buf][p][1], fb[buf][p][2], fb[buf][p][3],
                    bAddr[p] + ko);
    };
    auto mma_all = [&](int buf) {
        #pragma unroll
        for (int mt = 0; mt < 4; mt++)
            #pragma unroll
            for (int nt = 0; nt < 8; nt++)
                mma_bf16(acc[mt][nt], fa[buf][mt], &fb[buf][nt >> 1][(nt & 1) * 2]);
    };

    load_chunk(0, 0);
    if (NC > 1) { load_chunk(1, 1); CP_WAIT1(); } else { CP_WAIT0(); }
    __syncthreads();
    ldsm_all(0, 0);

    int stg = 0;
    for (int i = 0; i < NC; i++) {
        if (i + 2 < NC) load_chunk(i + 2, (stg + 2) % NSTG);
        const uint32_t soff = stg * STAGE_BYTES;
        #pragma unroll
        for (int kk = 0; kk < 3; kk++) {
            ldsm_all((kk + 1) & 1, soff + (kk + 1) * 32);
            mma_all(kk & 1);
        }
        if (i + 1 < NC) {
            if (i + 2 < NC) CP_WAIT1(); else CP_WAIT0();
            __syncthreads();
            ldsm_all(0, ((stg + 1) % NSTG) * STAGE_BYTES);
            mma_all(1);
        } else {
            mma_all(1);
        }
        stg = (stg + 1) % NSTG;
    }
    __syncthreads();

    const int cbase = bn * 256 + wn * 64;
    if (!EPILN) {
        #pragma unroll
        for (int mt = 0; mt < 4; mt++) {
            #pragma unroll
            for (int rr = 0; rr < 2; rr++) {
                int r = bm * 128 + wr * 64 + mt * 16 + gr + rr * 8;
                const float* rrow = RESID ? (resid + (size_t)r * ldc + cbase) : nullptr;
                #pragma unroll
                for (int nt = 0; nt < 8; nt++) {
                    int ci = nt * 8 + 2 * gc;
                    float v0 = acc[mt][nt][rr*2 + 0] + bias[cbase + ci];
                    float v1 = acc[mt][nt][rr*2 + 1] + bias[cbase + ci + 1];
                    if (RESID) {
                        float2 rv = *(const float2*)(rrow + ci);
                        v0 += rv.x; v1 += rv.y;
                    }
                    if (ACT == 1) { v0 = fmaxf(v0, 0.f); v1 = fmaxf(v1, 0.f); }
                    if (OBF) {
                        bf16* crow = (bf16*)Cv + (size_t)r * ldc + cbase;
                        __nv_bfloat162 bv;
                        bv.x = __float2bfloat16_rn(v0);
                        bv.y = __float2bfloat16_rn(v1);
                        *(__nv_bfloat162*)(crow + ci) = bv;
                    } else {
                        float* crow = (float*)Cv + (size_t)r * ldc + cbase;
                        *(float2*)(crow + ci) = make_float2(v0, v1);
                    }
                }
            }
        }
    } else {
        float* red = (float*)smem;
        #pragma unroll
        for (int mt = 0; mt < 4; mt++) {
            #pragma unroll
            for (int rr = 0; rr < 2; rr++) {
                int rl = wr * 64 + mt * 16 + rr * 8 + gr;
                int r  = bm * 128 + rl;
                const float* rrow = resid + (size_t)r * ldc + cbase;
                float* crow = (float*)Cv + (size_t)r * ldc + cbase;
                float s = 0.f, sq = 0.f;
                #pragma unroll
                for (int nt = 0; nt < 8; nt++) {
                    int ci = nt * 8 + 2 * gc;
                    float2 rv = *(const float2*)(rrow + ci);
                    float v0 = acc[mt][nt][rr*2 + 0] + bias[cbase + ci]     + rv.x;
                    float v1 = acc[mt][nt][rr*2 + 1] + bias[cbase + ci + 1] + rv.y;
                    acc[mt][nt][rr*2 + 0] = v0;
                    acc[mt][nt][rr*2 + 1] = v1;
                    *(float2*)(crow + ci) = make_float2(v0, v1);
                    s += v0 + v1; sq += v0*v0 + v1*v1;
                }
                s  += __shfl_xor_sync(0xffffffffu, s, 1);
                sq += __shfl_xor_sync(0xffffffffu, sq, 1);
                s  += __shfl_xor_sync(0xffffffffu, s, 2);
                sq += __shfl_xor_sync(0xffffffffu, sq, 2);
                if (gc == 0) {
                    red[rl * 8 + wn * 2 + 0] = s;
                    red[rl * 8 + wn * 2 + 1] = sq;
                }
            }
        }
        __syncthreads();
        #pragma unroll
        for (int mt = 0; mt < 4; mt++) {
            #pragma unroll
            for (int rr = 0; rr < 2; rr++) {
                int rl = wr * 64 + mt * 16 + rr * 8 + gr;
                int r  = bm * 128 + rl;
                float s  = red[rl*8+0] + red[rl*8+2] + red[rl*8+4] + red[rl*8+6];
                float sq = red[rl*8+1] + red[rl*8+3] + red[rl*8+5] + red[rl*8+7];
                float mean = s * (1.0f/Dn);
                float var  = sq * (1.0f/Dn) - mean*mean;
                float rstd = rsqrtf(var + 1e-5f);
                bf16* hrow = hout + (size_t)r * Dn + cbase;
                #pragma unroll
                for (int nt = 0; nt < 8; nt++) {
                    int ci = nt * 8 + 2 * gc;
                    float g0 = lng[cbase + ci], g1 = lng[cbase + ci + 1];
                    float be0 = lnb[cbase + ci], be1 = lnb[cbase + ci + 1];
                    float u0 = (acc[mt][nt][rr*2+0] - mean) * rstd * g0 + be0;
                    float u1 = (acc[mt][nt][rr*2+1] - mean) * rstd * g1 + be1;
                    __nv_bfloat162 bv;
                    bv.x = __float2bfloat16_rn(u0);
                    bv.y = __float2bfloat16_rn(u1);
                    *(__nv_bfloat162*)(hrow + ci) = bv;
                }
            }
        }
    }
}

// ======== SMALL kernel (R13): 128x128 tile, 128 thr, 2 CTAs/SM — FF2 ========
static constexpr int TILE_A_SM = 128 * LDSB;               // 9216
static constexpr int TILE_B_SM = 128 * LDSB;               // 9216
static constexpr int STAGE_SM  = TILE_A_SM + TILE_B_SM;    // 18432 bf16
static constexpr int STAGE_SM_BYTES = STAGE_SM * 2;        // 36864
static constexpr int SM_SMEM_BYTES = NSTG * STAGE_SM_BYTES; // 110592

template<int ACT, bool RESID, bool OBF>
__global__ __launch_bounds__(128, 2)
void gemm_tc_sm(const bf16* __restrict__ A, int lda,
                const bf16* __restrict__ Bt,
                const float* __restrict__ bias,
                const float* __restrict__ resid,
                void* __restrict__ Cv, int ldc, int K) {
    extern __shared__ bf16 smem[];
    const uint32_t sbase = smem_u32(smem);
    const int tid = threadIdx.x;
    const int wid = tid >> 5, lane = tid & 31;
    const int wr = wid >> 1, wn = wid & 1;      // 2x2 warp grid, 64x64 warp tiles
    const int gr = lane >> 2, gc = lane & 3;
    const int bm = blockIdx.y, bn = blockIdx.x;

    const bf16* Ag0 = A  + (size_t)bm * 128 * lda;
    const bf16* Bg0 = Bt + (size_t)bn * 128 * K;
    const int NC = K / KC;

    float acc[4][8][4];
    #pragma unroll
    for (int mt = 0; mt < 4; mt++)
        #pragma unroll
        for (int nt = 0; nt < 8; nt++)
            #pragma unroll
            for (int i = 0; i < 4; i++) acc[mt][nt][i] = 0.f;

    uint32_t aAddr[4], bAddr[4];
    {
        int arow = (lane & 15);
        int acol = (lane >> 4) * 8;
        #pragma unroll
        for (int mt = 0; mt < 4; mt++) {
            int r = wr*64 + mt*16 + arow;
            aAddr[mt] = sbase + (uint32_t)(r * LDSB + acol) * 2;
        }
        int brow = ((lane >> 4) * 8) + (lane & 7);
        int bcol = ((lane >> 3) & 1) * 8;
        #pragma unroll
        for (int p = 0; p < 4; p++) {
            int r = wn*64 + p*16 + brow;
            bAddr[p] = sbase + (uint32_t)(TILE_A_SM + r * LDSB + bcol) * 2;
        }
    }

    auto load_chunk = [&](int kc, int s) {
        bf16* As = smem + s * STAGE_SM;
        bf16* Bs = As + TILE_A_SM;
        const bf16* Agc = Ag0 + kc * KC;
        const bf16* Bgc = Bg0 + kc * KC;
        #pragma unroll
        for (int j = 0; j < 8; j++) {
            int slot = tid + 128 * j;
            int row  = slot >> 3, c8 = slot & 7;
            uint32_t da = smem_u32(As + row * LDSB + c8 * 8);
            CP_ASYNC16(da, Agc + (size_t)row * lda + c8 * 8);
            uint32_t db = smem_u32(Bs + row * LDSB + c8 * 8);
            CP_ASYNC16(db, Bgc + (size_t)row * K + c8 * 8);
        }
        CP_COMMIT();
    };

    uint32_t fa[2][4][4], fb[2][4][4];
    auto ldsm_all = [&](int buf, uint32_t ko) {
        #pragma unroll
        for (int mt = 0; mt < 4; mt++)
            LDSM_X4(fa[buf][mt][0], fa[buf][mt][1], fa[buf][mt][2], fa[buf][mt][3],
                    aAddr[mt] + ko);
        #pragma unroll
        for (int p = 0; p < 4; p++)
            LDSM_X4(fb[buf][p][0], fb[buf][p][1], fb[buf][p][2], fb[buf][p][3],
                    bAddr[p] + ko);
    };
    auto mma_all = [&](int buf) {
        #pragma unroll
        for (int mt = 0; mt < 4; mt++)
            #pragma unroll
            for (int nt = 0; nt < 8; nt++)
                mma_bf16(acc[mt][nt], fa[buf][mt], &fb[buf][nt >> 1][(nt & 1) * 2]);
    };

    load_chunk(0, 0);
    if (NC > 1) { load_chunk(1, 1); CP_WAIT1(); } else { CP_WAIT0(); }
    __syncthreads();
    ldsm_all(0, 0);

    int stg = 0;
    for (int i = 0; i < NC; i++) {
        if (i + 2 < NC) load_chunk(i + 2, (stg + 2) % NSTG);
        const uint32_t soff = stg * STAGE_SM_BYTES;
        #pragma unroll
        for (int kk = 0; kk < 3; kk++) {
            ldsm_all((kk + 1) & 1, soff + (kk + 1) * 32);
            mma_all(kk & 1);
        }
        if (i + 1 < NC) {
            if (i + 2 < NC) CP_WAIT1(); else CP_WAIT0();
            __syncthreads();
            ldsm_all(0, ((stg + 1) % NSTG) * STAGE_SM_BYTES);
            mma_all(1);
        } else {
            mma_all(1);
        }
        stg = (stg + 1) % NSTG;
    }

    const int cbase = bn * 128 + wn * 64;
    #pragma unroll
    for (int mt = 0; mt < 4; mt++) {
        #pragma unroll
        for (int rr = 0; rr < 2; rr++) {
            int r = bm * 128 + wr * 64 + mt * 16 + gr + rr * 8;
            const float* rrow = RESID ? (resid + (size_t)r * ldc + cbase) : nullptr;
            #pragma unroll
            for (int nt = 0; nt < 8; nt++) {
                int ci = nt * 8 + 2 * gc;
                float v0 = acc[mt][nt][rr*2 + 0] + bias[cbase + ci];
                float v1 = acc[mt][nt][rr*2 + 1] + bias[cbase + ci + 1];
                if (RESID) {
                    float2 rv = *(const float2*)(rrow + ci);
                    v0 += rv.x; v1 += rv.y;
                }
                if (ACT == 1) { v0 = fmaxf(v0, 0.f); v1 = fmaxf(v1, 0.f); }
                if (OBF) {
                    bf16* crow = (bf16*)Cv + (size_t)r * ldc + cbase;
                    __nv_bfloat162 bv;
                    bv.x = __float2bfloat16_rn(v0);
                    bv.y = __float2bfloat16_rn(v1);
                    *(__nv_bfloat162*)(crow + ci) = bv;
                } else {
                    float* crow = (float*)Cv + (size_t)r * ldc + cbase;
                    *(float2*)(crow + ci) = make_float2(v0, v1);
                }
            }
        }
    }
}

// ======== PERSISTENT-B kernel: K=256, 128x128 tile x TPB m-tiles, 128 thr, 2 CTAs/SM ========
// B (128 cols x 256 K) resident in smem; A streamed 2-stage; epilogue overlapped.
#define TPB 4
static constexpr int NCH4      = 4;                  // 256 / KC
static constexpr int BCH_BF    = 128 * LDSB;         // bf16 per B chunk
static constexpr int BCH_BYTES = BCH_BF * 2;         // 18432
static constexpr int PB_BYTES  = NCH4 * BCH_BYTES;   // 73728
static constexpr int PA_BF     = 128 * LDSB;
static constexpr int PA_BYTES  = PA_BF * 2;          // 18432
static constexpr int P_SMEM_BYTES = PB_BYTES + 2 * PA_BYTES;  // 110592

template<int ACT>
__global__ __launch_bounds__(128, 2)
void gemm_tc_p(const bf16* __restrict__ A, int lda,
               const bf16* __restrict__ Bt,
               const float* __restrict__ bias,
               bf16* __restrict__ C, int ldc) {
    extern __shared__ bf16 smem[];
    const uint32_t sbase = smem_u32(smem);
    const int tid = threadIdx.x;
    const int wid = tid >> 5, lane = tid & 31;
    const int wr = wid >> 1, wn = wid & 1;      // 2x2 warp grid, 64x64 warp tiles
    const int gr = lane >> 2, gc = lane & 3;
    const int bn = blockIdx.x;
    const int bm0 = blockIdx.y * TPB;

    const bf16* Bg0 = Bt + (size_t)bn * 128 * 256;

    float acc[4][8][4];
    #pragma unroll
    for (int mt = 0; mt < 4; mt++)
        #pragma unroll
        for (int nt = 0; nt < 8; nt++)
            #pragma unroll
            for (int i = 0; i < 4; i++) acc[mt][nt][i] = 0.f;

    uint32_t aAddr[4], bAddr[4];
    {
        int arow = (lane & 15);
        int acol = (lane >> 4) * 8;
        #pragma unroll
        for (int mt = 0; mt < 4; mt++) {
            int r = wr*64 + mt*16 + arow;
            aAddr[mt] = sbase + PB_BYTES + (uint32_t)(r * LDSB + acol) * 2;
        }
        int brow = ((lane >> 4) * 8) + (lane & 7);
        int bcol = ((lane >> 3) & 1) * 8;
        #pragma unroll
        for (int p = 0; p < 4; p++) {
            int r = wn*64 + p*16 + brow;
            bAddr[p] = sbase + (uint32_t)(r * LDSB + bcol) * 2;
        }
    }

    // load one A chunk (global chunk index g): tile = g>>2, kc = g&3, stage = g&1
    auto load_A = [&](int g) {
        int tile = g >> 2, kc = g & 3, st = g & 1;
        bf16* As = smem + PB_BYTES/2 + st * PA_BF;
        const bf16* Agc = A + (size_t)(bm0 + tile) * 128 * lda + kc * KC;
        #pragma unroll
        for (int j = 0; j < 8; j++) {
            int slot = tid + 128 * j;
            int row  = slot >> 3, c8 = slot & 7;
            uint32_t da = smem_u32(As + row * LDSB + c8 * 8);
            CP_ASYNC16(da, Agc + (size_t)row * lda + c8 * 8);
        }
        CP_COMMIT();
    };

    // prologue: all B chunks + A chunk 0 in one group
    {
        #pragma unroll
        for (int c = 0; c < NCH4; c++) {
            bf16* Bs = smem + c * BCH_BF;
            const bf16* Bgc = Bg0 + c * KC;
            #pragma unroll
            for (int j = 0; j < 8; j++) {
                int slot = tid + 128 * j;
                int row  = slot >> 3, c8 = slot & 7;
                uint32_t db = smem_u32(Bs + row * LDSB + c8 * 8);
                CP_ASYNC16(db, Bgc + (size_t)row * 256 + c8 * 8);
            }
        }
        // A chunk 0 (no separate commit; part of group 0)
        bf16* As = smem + PB_BYTES/2;
        const bf16* Agc = A + (size_t)bm0 * 128 * lda;
        #pragma unroll
        for (int j = 0; j < 8; j++) {
            int slot = tid + 128 * j;
            int row  = slot >> 3, c8 = slot & 7;
            uint32_t da = smem_u32(As + row * LDSB + c8 * 8);
            CP_ASYNC16(da, Agc + (size_t)row * lda + c8 * 8);
        }
        CP_COMMIT();
        CP_WAIT0();
        __syncthreads();
    }

    uint32_t fa[2][4][4], fb[2][4][4];
    auto ldsm_k = [&](int buf, uint32_t aoff, uint32_t boff, int kk) {
        const uint32_t ko = (uint32_t)kk * 32;
        #pragma unroll
        for (int mt = 0; mt < 4; mt++)
            LDSM_X4(fa[buf][mt][0], fa[buf][mt][1], fa[buf][mt][2], fa[buf][mt][3],
                    aAddr[mt] + aoff + ko);
        #pragma unroll
        for (int p = 0; p < 4; p++)
            LDSM_X4(fb[buf][p][0], fb[buf][p][1], fb[buf][p][2], fb[buf][p][3],
                    bAddr[p] + boff + ko);
    };
    auto mma_all = [&](int buf) {
        #pragma unroll
        for (int mt = 0; mt < 4; mt++)
            #pragma unroll
            for (int nt = 0; nt < 8; nt++)
                mma_bf16(acc[mt][nt], fa[buf][mt], &fb[buf][nt >> 1][(nt & 1) * 2]);
    };

    auto epilogue = [&](int tile) {
        const int cbase = bn * 128 + wn * 64;
        #pragma unroll
        for (int mt = 0; mt < 4; mt++) {
            #pragma unroll
            for (int rr = 0; rr < 2; rr++) {
                int r = (bm0 + tile) * 128 + wr * 64 + mt * 16 + gr + rr * 8;
                bf16* crow = C + (size_t)r * ldc + cbase;
                #pragma unroll
                for (int nt = 0; nt < 8; nt++) {
                    int ci = nt * 8 + 2 * gc;
                    float v0 = acc[mt][nt][rr*2 + 0] + bias[cbase + ci];
                    float v1 = acc[mt][nt][rr*2 + 1] + bias[cbase + ci + 1];
                    if (ACT == 1) { v0 = fmaxf(v0, 0.f); v1 = fmaxf(v1, 0.f); }
                    __nv_bfloat162 bv;
                    bv.x = __float2bfloat16_rn(v0);
                    bv.y = __float2bfloat16_rn(v1);
                    *(__nv_bfloat162*)(crow + ci) = bv;
                    acc[mt][nt][rr*2 + 0] = 0.f;
                    acc[mt][nt][rr*2 + 1] = 0.f;
                }
            }
        }
    };

    const int TOT = TPB * NCH4;
    for (int g = 0; g < TOT; g++) {
        if (g + 1 < TOT) load_A(g + 1);               // stage (g+1)&1 != g&1
        const uint32_t aoff = (uint32_t)(g & 1) * PA_BYTES;
        const uint32_t boff = (uint32_t)(g & 3) * BCH_BYTES;
        // chunk compute with in-chunk fragment double-buffering
        ldsm_k(0, aoff, boff, 0);
        #pragma unroll
        for (int kk = 0; kk < 3; kk++) {
            ldsm_k((kk + 1) & 1, aoff, boff, kk + 1);
            mma_all(kk & 1);
        }
        mma_all(1);
        if ((g & 3) == 3) epilogue(g >> 2);           // overlaps in-flight A load
        if (g + 1 < TOT) { CP_WAIT0(); __syncthreads(); }
    }
}

// ---------------- fused build_x + first LN: 1 warp per row ----------------
__global__ void build_ln_kernel(const float* __restrict__ term,
                                const float* __restrict__ pred,
                                const float* __restrict__ gam,
                                const float* __restrict__ bet,
                                float* __restrict__ x, bf16* __restrict__ h) {
    int warp = (blockIdx.x * blockDim.x + threadIdx.x) >> 5;
    int lane = threadIdx.x & 31;
    if (warp >= MROWS) return;
    int s3 = warp % 3;
    int n = warp / 3;
    int t = n / Bn;
    int b = n % Bn;
    const int srcT[3][3] = {{1,2,0},{0,2,1},{1,0,2}};
    const int srcP[3][3] = {{0,2,-1},{0,1,-1},{1,2,-1}};
    const float sgn[3][3] = {{-1.f,-1.f,0.f},{1.f,-1.f,0.f},{1.f,1.f,0.f}};
    int tt = srcT[t][s3];
    int pp = srcP[t][s3];
    float sg = sgn[t][s3];
    const float* trow = term + ((size_t)tt*Bn + b)*Dn + lane*8;
    float4 a0 = *(const float4*)(trow);
    float4 a1 = *(const float4*)(trow + 4);
    float vals[8] = {a0.x,a0.y,a0.z,a0.w,a1.x,a1.y,a1.z,a1.w};
    if (pp >= 0) {
        const float* prow = pred + ((size_t)pp*Bn + b)*Dn + lane*8;
        float4 p0 = *(const float4*)(prow);
        float4 p1 = *(const float4*)(prow + 4);
        float pv[8] = {p0.x,p0.y,p0.z,p0.w,p1.x,p1.y,p1.z,p1.w};
        #pragma unroll
        for (int i = 0; i < 8; i++) vals[i] += sg * pv[i];
    }
    float* xrow = x + (size_t)warp * Dn + lane*8;
    *(float4*)(xrow)     = make_float4(vals[0],vals[1],vals[2],vals[3]);
    *(float4*)(xrow + 4) = make_float4(vals[4],vals[5],vals[6],vals[7]);
    float s = 0.f, sq = 0.f;
    #pragma unroll
    for (int i = 0; i < 8; i++) { s += vals[i]; sq += vals[i]*vals[i]; }
    #pragma unroll
    for (int o = 16; o > 0; o >>= 1) {
        s  += __shfl_xor_sync(0xffffffffu, s,  o);
        sq += __shfl_xor_sync(0xffffffffu, sq, o);
    }
    float mean = s * (1.0f/Dn);
    float var  = sq * (1.0f/Dn) - mean*mean;
    float rstd = rsqrtf(var + 1e-5f);
    float4 g0 = *(const float4*)(gam + lane*8);
    float4 g1 = *(const float4*)(gam + lane*8 + 4);
    float4 b0 = *(const float4*)(bet + lane*8);
    float4 b1 = *(const float4*)(bet + lane*8 + 4);
    float gs[8] = {g0.x,g0.y,g0.z,g0.w,g1.x,g1.y,g1.z,g1.w};
    float bs[8] = {b0.x,b0.y,b0.z,b0.w,b1.x,b1.y,b1.z,b1.w};
    __nv_bfloat162 ov[4];
    #pragma unroll
    for (int i = 0; i < 4; i++) {
        float u0 = (vals[2*i]  -mean)*rstd*gs[2*i]   + bs[2*i];
        float u1 = (vals[2*i+1]-mean)*rstd*gs[2*i+1] + bs[2*i+1];
        ov[i].x = __float2bfloat16_rn(u0);
        ov[i].y = __float2bfloat16_rn(u1);
    }
    *(uint4*)(h + (size_t)warp * Dn + lane*8) = *(uint4*)ov;
}

// ---------------- standalone layernorm: 1 warp per row (fp32 in, bf16 out) ----------------
__global__ void ln_kernel(const float* __restrict__ x,
                          const float* __restrict__ gam,
                          const float* __restrict__ bet,
                          bf16* __restrict__ out) {
    int warp = (blockIdx.x * blockDim.x + threadIdx.x) >> 5;
    int lane = threadIdx.x & 31;
    if (warp >= MROWS) return;
    const float* row = x + (size_t)warp * Dn;
    float4 a0 = *(const float4*)(row + lane*8);
    float4 a1 = *(const float4*)(row + lane*8 + 4);
    float vals[8] = {a0.x,a0.y,a0.z,a0.w,a1.x,a1.y,a1.z,a1.w};
    float s = 0.f, sq = 0.f;
    #pragma unroll
    for (int i = 0; i < 8; i++) { s += vals[i]; sq += vals[i]*vals[i]; }
    #pragma unroll
    for (int o = 16; o > 0; o >>= 1) {
        s  += __shfl_xor_sync(0xffffffffu, s,  o);
        sq += __shfl_xor_sync(0xffffffffu, sq, o);
    }
    float mean = s * (1.0f/Dn);
    float var  = sq * (1.0f/Dn) - mean*mean;
    float rstd = rsqrtf(var + 1e-5f);
    float4 g0 = *(const float4*)(gam + lane*8);
    float4 g1 = *(const float4*)(gam + lane*8 + 4);
    float4 b0 = *(const float4*)(bet + lane*8);
    float4 b1 = *(const float4*)(bet + lane*8 + 4);
    float gs[8] = {g0.x,g0.y,g0.z,g0.w,g1.x,g1.y,g1.z,g1.w};
    float bs[8] = {b0.x,b0.y,b0.z,b0.w,b1.x,b1.y,b1.z,b1.w};
    __nv_bfloat162 ov[4];
    #pragma unroll
    for (int i = 0; i < 4; i++) {
        float u0 = (vals[2*i]  -mean)*rstd*gs[2*i]   + bs[2*i];
        float u1 = (vals[2*i+1]-mean)*rstd*gs[2*i+1] + bs[2*i+1];
        ov[i].x = __float2bfloat16_rn(u0);
        ov[i].y = __float2bfloat16_rn(u1);
    }
    *(uint4*)(out + (size_t)warp * Dn + lane*8) = *(uint4*)ov;
}

// ---------------- attention on fused qkv buffer (bf16): 1 warp per (n, head) ----------------
__global__ void attn_kernel(const bf16* __restrict__ qkv, bf16* __restrict__ o) {
    int widx = (blockIdx.x * blockDim.x + threadIdx.x) >> 5;
    int lane = threadIdx.x & 31;
    if (widx >= NG * Hn) return;
    int n = widx >> 3;
    int h = widx & 7;
    size_t rb = (size_t)n * 3 * (3*Dn) + h*DHn + lane;
    float qs[3], ks[3], vs[3];
    #pragma unroll
    for (int s = 0; s < 3; s++) {
        qs[s] = __bfloat162float(qkv[rb + (size_t)s*(3*Dn)]);
        ks[s] = __bfloat162float(qkv[rb + (size_t)s*(3*Dn) + Dn]);
        vs[s] = __bfloat162float(qkv[rb + (size_t)s*(3*Dn) + 2*Dn]);
    }
    float sc[3][3];
    #pragma unroll
    for (int s = 0; s < 3; s++)
        #pragma unroll
        for (int t = 0; t < 3; t++) {
            float p = qs[s]*ks[t];
            #pragma unroll
            for (int off = 16; off > 0; off >>= 1)
                p += __shfl_xor_sync(0xffffffffu, p, off);
            sc[s][t] = p * SCALE_F;
        }
    #pragma unroll
    for (int s = 0; s < 3; s++) {
        float m = fmaxf(sc[s][0], fmaxf(sc[s][1], sc[s][2]));
        float e0 = __expf(sc[s][0]-m);
        float e1 = __expf(sc[s][1]-m);
        float e2 = __expf(sc[s][2]-m);
        float inv = 1.0f/(e0+e1+e2);
        float os = (e0*vs[0] + e1*vs[1] + e2*vs[2]) * inv;
        o[(size_t)(n*3+s)*Dn + h*DHn + lane] = __float2bfloat16_rn(os);
    }
}

// ---------------- one-shot transpose+convert of all weights (both layers) ----------------
__global__ void transpose_all(const float* __restrict__ Wq, const float* __restrict__ Wk,
                              const float* __restrict__ Wv, const float* __restrict__ Wo,
                              const float* __restrict__ W1, const float* __restrict__ W2,
                              bf16* __restrict__ wt) {
    __shared__ float t[32][33];
    int bid = blockIdx.x;
    int l = bid / 768;
    int tt = bid % 768;
    const float* in; bf16* out; int N, n0, k0, outld;
    if (tt < 192) {
        int which = tt / 64; int q = tt % 64;
        const float* Ws[3] = {Wq, Wk, Wv};
        in = Ws[which] + (size_t)l*Dn*Dn;
        out = wt + (size_t)l*WT_LAYER + which*Dn*Dn;
        N = Dn; outld = Dn;
        n0 = (q & 7) * 32; k0 = (q >> 3) * 32;
    } else if (tt < 256) {
        int q = tt - 192;
        in = Wo + (size_t)l*Dn*Dn;
        out = wt + (size_t)l*WT_LAYER + 196608;
        N = Dn; outld = Dn;
        n0 = (q & 7) * 32; k0 = (q >> 3) * 32;
    } else if (tt < 512) {
        int q = tt - 256;
        in = W1 + (size_t)l*Dn*FFn;
        out = wt + (size_t)l*WT_LAYER + 262144;
        N = FFn; outld = Dn;
        n0 = (q & 31) * 32; k0 = (q >> 5) * 32;
    } else {
        int q = tt - 512;
        in = W2 + (size_t)l*FFn*Dn;
        out = wt + (size_t)l*WT_LAYER + 524288;
        N = Dn; outld = FFn;
        n0 = (q & 7) * 32; k0 = (q >> 3) * 32;
    }
    int tx = threadIdx.x, ty = threadIdx.y;   // 32 x 8
    #pragma unroll
    for (int i = ty; i < 32; i += 8)
        t[i][tx] = in[(size_t)(k0+i)*N + n0+tx];
    __syncthreads();
    #pragma unroll
    for (int i = ty; i < 32; i += 8)
        out[(size_t)(n0+i)*outld + k0+tx] = __float2bfloat16_rn(t[tx][i]);
}

__global__ void concat_bias_kernel(const float* __restrict__ bq, const float* __restrict__ bk,
                                   const float* __restrict__ bv, float* __restrict__ out) {
    int i = blockIdx.x*blockDim.x + threadIdx.x;
    if (i >= 2*3*Dn) return;
    int l = i / (3*Dn);
    int j = i % (3*Dn);
    float v;
    if (j < Dn)        v = bq[l*Dn + j];
    else if (j < 2*Dn) v = bk[l*Dn + j-Dn];
    else               v = bv[l*Dn + j-2*Dn];
    out[i] = v;
}

// ---------------- fused final LN + mean-pool: 1 warp per group ----------------
__global__ void ln_mean_kernel(const float* __restrict__ x,
                               const float* __restrict__ gam,
                               const float* __restrict__ bet,
                               float* __restrict__ out) {
    int warp = (blockIdx.x * blockDim.x + threadIdx.x) >> 5;
    int lane = threadIdx.x & 31;
    if (warp >= NG) return;
    float4 g0 = *(const float4*)(gam + lane*8);
    float4 g1 = *(const float4*)(gam + lane*8 + 4);
    float4 b0 = *(const float4*)(bet + lane*8);
    float4 b1 = *(const float4*)(bet + lane*8 + 4);
    float gs[8] = {g0.x,g0.y,g0.z,g0.w,g1.x,g1.y,g1.z,g1.w};
    float bs[8] = {b0.x,b0.y,b0.z,b0.w,b1.x,b1.y,b1.z,b1.w};
    float avg[8] = {0,0,0,0,0,0,0,0};
    #pragma unroll
    for (int s3 = 0; s3 < 3; s3++) {
        const float* row = x + ((size_t)warp*3 + s3) * Dn;
        float4 a0 = *(const float4*)(row + lane*8);
        float4 a1 = *(const float4*)(row + lane*8 + 4);
        float vals[8] = {a0.x,a0.y,a0.z,a0.w,a1.x,a1.y,a1.z,a1.w};
        float s = 0.f, sq = 0.f;
        #pragma unroll
        for (int i = 0; i < 8; i++) { s += vals[i]; sq += vals[i]*vals[i]; }
        #pragma unroll
        for (int o = 16; o > 0; o >>= 1) {
            s  += __shfl_xor_sync(0xffffffffu, s,  o);
            sq += __shfl_xor_sync(0xffffffffu, sq, o);
        }
        float mean = s * (1.0f/Dn);
        float var  = sq * (1.0f/Dn) - mean*mean;
        float rstd = rsqrtf(var + 1e-5f);
        #pragma unroll
        for (int i = 0; i < 8; i++)
            avg[i] += ((vals[i]-mean)*rstd*gs[i] + bs[i]) * (1.0f/3.0f);
    }
    float* orow = out + (size_t)warp * Dn;
    *(float4*)(orow + lane*8)     = make_float4(avg[0],avg[1],avg[2],avg[3]);
    *(float4*)(orow + lane*8 + 4) = make_float4(avg[4],avg[5],avg[6],avg[7]);
}

// ---------------- host ----------------
extern "C" void kernel_launch(void* const* d_in, const int* in_sizes, int n_in,
                              void* d_out, int out_size) {
    const float* term  = (const float*)d_in[0];
    const float* pred  = (const float*)d_in[1];
    const float* Wq    = (const float*)d_in[2];
    const float* Wk    = (const float*)d_in[3];
    const float* Wv    = (const float*)d_in[4];
    const float* Wo    = (const float*)d_in[5];
    const float* bq    = (const float*)d_in[6];
    const float* bk    = (const float*)d_in[7];
    const float* bv    = (const float*)d_in[8];
    const float* bo    = (const float*)d_in[9];
    const float* ln1g  = (const float*)d_in[10];
    const float* ln1b  = (const float*)d_in[11];
    const float* ln2g  = (const float*)d_in[12];
    const float* ln2b  = (const float*)d_in[13];
    const float* W1    = (const float*)d_in[14];
    const float* b1    = (const float*)d_in[15];
    const float* W2    = (const float*)d_in[16];
    const float* b2    = (const float*)d_in[17];
    const float* lnfg  = (const float*)d_in[18];
    const float* lnfb  = (const float*)d_in[19];
    float* out = (float*)d_out;

    float *x, *bqkv;
    bf16 *h, *qkv, *o, *f, *wt;
    cudaGetSymbolAddress((void**)&x,   g_x);
    cudaGetSymbolAddress((void**)&h,   g_h);
    cudaGetSymbolAddress((void**)&qkv, g_qkv);
    cudaGetSymbolAddress((void**)&o,   g_o);
    cudaGetSymbolAddress((void**)&f,   g_f);
    cudaGetSymbolAddress((void**)&wt,  g_wt);
    cudaGetSymbolAddress((void**)&bqkv,g_bqkv);

    cudaFuncSetAttribute(gemm_tc<0,true ,false,true >, cudaFuncAttributeMaxDynamicSharedMemorySize, GEMM_SMEM_BYTES);
    cudaFuncSetAttribute(gemm_tc_sm<0,true ,false>, cudaFuncAttributeMaxDynamicSharedMemorySize, SM_SMEM_BYTES);
    cudaFuncSetAttribute(gemm_tc_p<0>, cudaFuncAttributeMaxDynamicSharedMemorySize, P_SMEM_BYTES);
    cudaFuncSetAttribute(gemm_tc_p<1>, cudaFuncAttributeMaxDynamicSharedMemorySize, P_SMEM_BYTES);

    // weight prep + fused build_x + LN1(layer0)
    transpose_all<<<2*768, dim3(32,8)>>>(Wq, Wk, Wv, Wo, W1, W2, wt);
    concat_bias_kernel<<<6, 256>>>(bq, bk, bv, bqkv);
    build_ln_kernel<<<MROWS/8, 256>>>(term, pred, ln1g, ln1b, x, h);

    const int MB  = MROWS / 128;        // 1152
    const int MBP = MB / TPB;           // 288
    for (int l = 0; l < NLn; l++) {
        const bf16* wl = wt + (size_t)l*WT_LAYER;

        // fused QKV GEMM (persistent-B): [MROWS,256] @ [256,768]
        gemm_tc_p<0><<<dim3(6, MBP), 128, P_SMEM_BYTES>>>(
            h, Dn, wl, bqkv + l*3*Dn, qkv, 3*Dn);

        // attention
        attn_kernel<<<NG*Hn/8, 256>>>(qkv, o);

        // output projection + residual -> x fp32, fused LN2 -> h bf16 (large EPILN)
        gemm_tc<0,true,false,true><<<dim3(1, MB), 256, GEMM_SMEM_BYTES>>>(
            o, Dn, wl + 196608, bo + l*Dn, x, x, Dn, Dn,
            ln2g + l*Dn, ln2b + l*Dn, h);

        // FFN up (relu, persistent-B): [MROWS,256] @ [256,1024]
        gemm_tc_p<1><<<dim3(8, MBP), 128, P_SMEM_BYTES>>>(
            h, Dn, wl + 262144, b1 + l*FFn, f, FFn);

        // FFN down + residual -> x fp32 (small kernel, 2 CTAs/SM)
        gemm_tc_sm<0,true,false><<<dim3(2, MB), 128, SM_SMEM_BYTES>>>(
            f, FFn, wl + 524288, b2 + l*Dn, x, x, Dn, FFn);

        // LN1 of next layer (standalone)
        if (l + 1 < NLn)
            ln_kernel<<<MROWS/8, 256>>>(x, ln1g + (l+1)*Dn, ln1b + (l+1)*Dn, h);
    }

    // fused final LN + mean pool
    ln_mean_kernel<<<NG/8, 256>>>(x, lnfg, lnfb, out);
    (void)in_sizes; (void)n_in; (void)out_size;
}

// round 16
// speedup vs baseline: 1.0664x; 1.0084x over previous
#include <cuda_runtime.h>
#include <cuda_bf16.h>
#include <cstdint>
#include <math.h>

// Problem constants
#define Tn   3
#define Bn   16384
#define Dn   256
#define Hn   8
#define DHn  32
#define NLn  2
#define FFn  1024
#define NG   (Tn*Bn)        // 49152 row-groups
#define MROWS (NG*3)        // 147456 total rows
#define SCALE_F 0.17677669529663687f   // 1/sqrt(32)

typedef __nv_bfloat16 bf16;

// ---------------- device scratch (allocation-free) ----------------
__device__ float g_x[MROWS*Dn];                 // residual stream (fp32)
__device__ bf16  g_h[MROWS*Dn];                 // LN output (bf16)
__device__ bf16  g_qkv[(size_t)MROWS*3*Dn];     // fused QKV output (bf16)
__device__ bf16  g_o[MROWS*Dn];                 // attention output (bf16)
__device__ bf16  g_f[(size_t)MROWS*FFn];        // FFN intermediate (bf16)
#define WT_LAYER 786432
__device__ bf16  g_wt[2*WT_LAYER];
__device__ float g_bqkv[2*3*Dn];                // concatenated qkv bias, both layers

// =================== helpers ===================
__device__ __forceinline__ uint32_t smem_u32(const void* p) {
    uint32_t a;
    asm("{ .reg .u64 t; cvta.to.shared.u64 t, %1; cvt.u32.u64 %0, t; }" : "=r"(a) : "l"(p));
    return a;
}
#define CP_ASYNC16(dst, src) \
    asm volatile("cp.async.cg.shared.global [%0], [%1], 16;" :: "r"(dst), "l"(src) : "memory")
#define CP_COMMIT() asm volatile("cp.async.commit_group;" ::: "memory")
#define CP_WAIT0()  asm volatile("cp.async.wait_group 0;" ::: "memory")
#define CP_WAIT1()  asm volatile("cp.async.wait_group 1;" ::: "memory")

#define LDSM_X4(r0, r1, r2, r3, addr) \
    asm volatile("ldmatrix.sync.aligned.m8n8.x4.shared.b16 {%0,%1,%2,%3}, [%4];" \
        : "=r"(r0), "=r"(r1), "=r"(r2), "=r"(r3) : "r"(addr))

// mma.sync m16n8k16 bf16
__device__ __forceinline__ void mma_bf16(float* c, const uint32_t* a, const uint32_t* b) {
    asm volatile(
        "mma.sync.aligned.m16n8k16.row.col.f32.bf16.bf16.f32 "
        "{%0,%1,%2,%3}, {%4,%5,%6,%7}, {%8,%9}, {%0,%1,%2,%3};"
        : "+f"(c[0]), "+f"(c[1]), "+f"(c[2]), "+f"(c[3])
        : "r"(a[0]), "r"(a[1]), "r"(a[2]), "r"(a[3]), "r"(b[0]), "r"(b[1]));
}

#define KC   64
#define LDSB 72
#define NSTG 3

// ======== SMALL kernel (R13): 128x128 tile, 128 thr, 2 CTAs/SM — QKV, FF1, FF2 ========
static constexpr int TILE_A_SM = 128 * LDSB;               // 9216
static constexpr int TILE_B_SM = 128 * LDSB;               // 9216
static constexpr int STAGE_SM  = TILE_A_SM + TILE_B_SM;    // 18432 bf16
static constexpr int STAGE_SM_BYTES = STAGE_SM * 2;        // 36864
static constexpr int SM_SMEM_BYTES = NSTG * STAGE_SM_BYTES; // 110592

template<int ACT, bool RESID, bool OBF>
__global__ __launch_bounds__(128, 2)
void gemm_tc_sm(const bf16* __restrict__ A, int lda,
                const bf16* __restrict__ Bt,
                const float* __restrict__ bias,
                const float* __restrict__ resid,
                void* __restrict__ Cv, int ldc, int K) {
    extern __shared__ bf16 smem[];
    const uint32_t sbase = smem_u32(smem);
    const int tid = threadIdx.x;
    const int wid = tid >> 5, lane = tid & 31;
    const int wr = wid >> 1, wn = wid & 1;      // 2x2 warp grid, 64x64 warp tiles
    const int gr = lane >> 2, gc = lane & 3;
    const int bm = blockIdx.y, bn = blockIdx.x;

    const bf16* Ag0 = A  + (size_t)bm * 128 * lda;
    const bf16* Bg0 = Bt + (size_t)bn * 128 * K;
    const int NC = K / KC;

    float acc[4][8][4];
    #pragma unroll
    for (int mt = 0; mt < 4; mt++)
        #pragma unroll
        for (int nt = 0; nt < 8; nt++)
            #pragma unroll
            for (int i = 0; i < 4; i++) acc[mt][nt][i] = 0.f;

    uint32_t aAddr[4], bAddr[4];
    {
        int arow = (lane & 15);
        int acol = (lane >> 4) * 8;
        #pragma unroll
        for (int mt = 0; mt < 4; mt++) {
            int r = wr*64 + mt*16 + arow;
            aAddr[mt] = sbase + (uint32_t)(r * LDSB + acol) * 2;
        }
        int brow = ((lane >> 4) * 8) + (lane & 7);
        int bcol = ((lane >> 3) & 1) * 8;
        #pragma unroll
        for (int p = 0; p < 4; p++) {
            int r = wn*64 + p*16 + brow;
            bAddr[p] = sbase + (uint32_t)(TILE_A_SM + r * LDSB + bcol) * 2;
        }
    }

    auto load_chunk = [&](int kc, int s) {
        bf16* As = smem + s * STAGE_SM;
        bf16* Bs = As + TILE_A_SM;
        const bf16* Agc = Ag0 + kc * KC;
        const bf16* Bgc = Bg0 + kc * KC;
        #pragma unroll
        for (int j = 0; j < 8; j++) {
            int slot = tid + 128 * j;
            int row  = slot >> 3, c8 = slot & 7;
            uint32_t da = smem_u32(As + row * LDSB + c8 * 8);
            CP_ASYNC16(da, Agc + (size_t)row * lda + c8 * 8);
            uint32_t db = smem_u32(Bs + row * LDSB + c8 * 8);
            CP_ASYNC16(db, Bgc + (size_t)row * K + c8 * 8);
        }
        CP_COMMIT();
    };

    uint32_t fa[2][4][4], fb[2][4][4];
    auto ldsm_all = [&](int buf, uint32_t ko) {
        #pragma unroll
        for (int mt = 0; mt < 4; mt++)
            LDSM_X4(fa[buf][mt][0], fa[buf][mt][1], fa[buf][mt][2], fa[buf][mt][3],
                    aAddr[mt] + ko);
        #pragma unroll
        for (int p = 0; p < 4; p++)
            LDSM_X4(fb[buf][p][0], fb[buf][p][1], fb[buf][p][2], fb[buf][p][3],
                    bAddr[p] + ko);
    };
    auto mma_all = [&](int buf) {
        #pragma unroll
        for (int mt = 0; mt < 4; mt++)
            #pragma unroll
            for (int nt = 0; nt < 8; nt++)
                mma_bf16(acc[mt][nt], fa[buf][mt], &fb[buf][nt >> 1][(nt & 1) * 2]);
    };

    load_chunk(0, 0);
    if (NC > 1) { load_chunk(1, 1); CP_WAIT1(); } else { CP_WAIT0(); }
    __syncthreads();
    ldsm_all(0, 0);

    int stg = 0;
    for (int i = 0; i < NC; i++) {
        if (i + 2 < NC) load_chunk(i + 2, (stg + 2) % NSTG);
        const uint32_t soff = stg * STAGE_SM_BYTES;
        #pragma unroll
        for (int kk = 0; kk < 3; kk++) {
            ldsm_all((kk + 1) & 1, soff + (kk + 1) * 32);
            mma_all(kk & 1);
        }
        if (i + 1 < NC) {
            if (i + 2 < NC) CP_WAIT1(); else CP_WAIT0();
            __syncthreads();
            ldsm_all(0, ((stg + 1) % NSTG) * STAGE_SM_BYTES);
            mma_all(1);
        } else {
            mma_all(1);
        }
        stg = (stg + 1) % NSTG;
    }

    const int cbase = bn * 128 + wn * 64;
    #pragma unroll
    for (int mt = 0; mt < 4; mt++) {
        #pragma unroll
        for (int rr = 0; rr < 2; rr++) {
            int r = bm * 128 + wr * 64 + mt * 16 + gr + rr * 8;
            const float* rrow = RESID ? (resid + (size_t)r * ldc + cbase) : nullptr;
            #pragma unroll
            for (int nt = 0; nt < 8; nt++) {
                int ci = nt * 8 + 2 * gc;
                float v0 = acc[mt][nt][rr*2 + 0] + bias[cbase + ci];
                float v1 = acc[mt][nt][rr*2 + 1] + bias[cbase + ci + 1];
                if (RESID) {
                    float2 rv = *(const float2*)(rrow + ci);
                    v0 += rv.x; v1 += rv.y;
                }
                if (ACT == 1) { v0 = fmaxf(v0, 0.f); v1 = fmaxf(v1, 0.f); }
                if (OBF) {
                    bf16* crow = (bf16*)Cv + (size_t)r * ldc + cbase;
                    __nv_bfloat162 bv;
                    bv.x = __float2bfloat16_rn(v0);
                    bv.y = __float2bfloat16_rn(v1);
                    *(__nv_bfloat162*)(crow + ci) = bv;
                } else {
                    float* crow = (float*)Cv + (size_t)r * ldc + cbase;
                    *(float2*)(crow + ci) = make_float2(v0, v1);
                }
            }
        }
    }
}

// ======== PERSISTENT-B EPILN kernel: proj (K=256, N=256), 256 thr, TPB m-tiles ========
// B resident (4 chunks x 256 x LDSB), A double-buffered, epilogue = resid + LN.
#define TPB 4
static constexpr int PE_BCH_BF    = 256 * LDSB;             // bf16 per B chunk
static constexpr int PE_BCH_BYTES = PE_BCH_BF * 2;          // 36864
static constexpr int PE_PB_BYTES  = 4 * PE_BCH_BYTES;       // 147456
static constexpr int PE_PA_BF     = 128 * LDSB;
static constexpr int PE_PA_BYTES  = PE_PA_BF * 2;           // 18432
static constexpr int PE_RED_BYTES = 128 * 8 * 4;            // 4096
static constexpr int PE_SMEM_BYTES = PE_PB_BYTES + 2*PE_PA_BYTES + PE_RED_BYTES; // 188416

__global__ __launch_bounds__(256)
void gemm_tc_pe(const bf16* __restrict__ A, int lda,
                const bf16* __restrict__ Bt,
                const float* __restrict__ bias,
                const float* __restrict__ resid,
                float* __restrict__ Cx, int ldc,
                const float* __restrict__ lng, const float* __restrict__ lnb,
                bf16* __restrict__ hout) {
    extern __shared__ bf16 smem[];
    const uint32_t sbase = smem_u32(smem);
    const int tid = threadIdx.x;
    const int wid = tid >> 5, lane = tid & 31;
    const int wr = wid >> 2, wn = wid & 3;      // 2x4 warp grid, 64x64 warp tiles
    const int gr = lane >> 2, gc = lane & 3;
    const int bm0 = blockIdx.y * TPB;

    float acc[4][8][4];
    #pragma unroll
    for (int mt = 0; mt < 4; mt++)
        #pragma unroll
        for (int nt = 0; nt < 8; nt++)
            #pragma unroll
            for (int i = 0; i < 4; i++) acc[mt][nt][i] = 0.f;

    uint32_t aAddr[4], bAddr[4];
    {
        int arow = (lane & 15);
        int acol = (lane >> 4) * 8;
        #pragma unroll
        for (int mt = 0; mt < 4; mt++) {
            int r = wr*64 + mt*16 + arow;
            aAddr[mt] = sbase + PE_PB_BYTES + (uint32_t)(r * LDSB + acol) * 2;
        }
        int brow = ((lane >> 4) * 8) + (lane & 7);
        int bcol = ((lane >> 3) & 1) * 8;
        #pragma unroll
        for (int p = 0; p < 4; p++) {
            int r = wn*64 + p*16 + brow;
            bAddr[p] = sbase + (uint32_t)(r * LDSB + bcol) * 2;
        }
    }

    auto load_A = [&](int g) {   // g: tile = g>>2, kc = g&3, stage = g&1
        int tile = g >> 2, kc = g & 3, st = g & 1;
        bf16* As = smem + PE_PB_BYTES/2 + st * PE_PA_BF;
        const bf16* Agc = A + (size_t)(bm0 + tile) * 128 * lda + kc * KC;
        #pragma unroll
        for (int j = 0; j < 4; j++) {
            int slot = tid + 256 * j;            // 1024 slots
            int row  = slot >> 3, c8 = slot & 7;
            uint32_t da = smem_u32(As + row * LDSB + c8 * 8);
            CP_ASYNC16(da, Agc + (size_t)row * lda + c8 * 8);
        }
        CP_COMMIT();
    };

    // prologue: all 4 B chunks (256 rows each) + A chunk 0
    {
        #pragma unroll
        for (int c = 0; c < 4; c++) {
            bf16* Bs = smem + c * PE_BCH_BF;
            const bf16* Bgc = Bt + c * KC;
            #pragma unroll
            for (int j = 0; j < 8; j++) {
                int slot = tid + 256 * j;        // 2048 slots per chunk
                int row  = slot >> 3, c8 = slot & 7;
                uint32_t db = smem_u32(Bs + row * LDSB + c8 * 8);
                CP_ASYNC16(db, Bgc + (size_t)row * 256 + c8 * 8);
            }
        }
        bf16* As = smem + PE_PB_BYTES/2;
        const bf16* Agc = A + (size_t)bm0 * 128 * lda;
        #pragma unroll
        for (int j = 0; j < 4; j++) {
            int slot = tid + 256 * j;
            int row  = slot >> 3, c8 = slot & 7;
            uint32_t da = smem_u32(As + row * LDSB + c8 * 8);
            CP_ASYNC16(da, Agc + (size_t)row * lda + c8 * 8);
        }
        CP_COMMIT();
        CP_WAIT0();
        __syncthreads();
    }

    uint32_t fa[2][4][4], fb[2][4][4];
    auto ldsm_k = [&](int buf, uint32_t aoff, uint32_t boff, int kk) {
        const uint32_t ko = (uint32_t)kk * 32;
        #pragma unroll
        for (int mt = 0; mt < 4; mt++)
            LDSM_X4(fa[buf][mt][0], fa[buf][mt][1], fa[buf][mt][2], fa[buf][mt][3],
                    aAddr[mt] + aoff + ko);
        #pragma unroll
        for (int p = 0; p < 4; p++)
            LDSM_X4(fb[buf][p][0], fb[buf][p][1], fb[buf][p][2], fb[buf][p][3],
                    bAddr[p] + boff + ko);
    };
    auto mma_all = [&](int buf) {
        #pragma unroll
        for (int mt = 0; mt < 4; mt++)
            #pragma unroll
            for (int nt = 0; nt < 8; nt++)
                mma_bf16(acc[mt][nt], fa[buf][mt], &fb[buf][nt >> 1][(nt & 1) * 2]);
    };

    float* red = (float*)(smem + (PE_PB_BYTES + 2*PE_PA_BYTES)/2);
    auto epilogue = [&](int tile) {
        const int cbase = wn * 64;
        __syncthreads();   // red reuse safety across tiles
        #pragma unroll
        for (int mt = 0; mt < 4; mt++) {
            #pragma unroll
            for (int rr = 0; rr < 2; rr++) {
                int rl = wr * 64 + mt * 16 + rr * 8 + gr;
                int r  = (bm0 + tile) * 128 + rl;
                const float* rrow = resid + (size_t)r * ldc + cbase;
                float* crow = Cx + (size_t)r * ldc + cbase;
                float s = 0.f, sq = 0.f;
                #pragma unroll
                for (int nt = 0; nt < 8; nt++) {
                    int ci = nt * 8 + 2 * gc;
                    float2 rv = *(const float2*)(rrow + ci);
                    float v0 = acc[mt][nt][rr*2 + 0] + bias[cbase + ci]     + rv.x;
                    float v1 = acc[mt][nt][rr*2 + 1] + bias[cbase + ci + 1] + rv.y;
                    acc[mt][nt][rr*2 + 0] = v0;
                    acc[mt][nt][rr*2 + 1] = v1;
                    *(float2*)(crow + ci) = make_float2(v0, v1);
                    s += v0 + v1; sq += v0*v0 + v1*v1;
                }
                s  += __shfl_xor_sync(0xffffffffu, s, 1);
                sq += __shfl_xor_sync(0xffffffffu, sq, 1);
                s  += __shfl_xor_sync(0xffffffffu, s, 2);
                sq += __shfl_xor_sync(0xffffffffu, sq, 2);
                if (gc == 0) {
                    red[rl * 8 + wn * 2 + 0] = s;
                    red[rl * 8 + wn * 2 + 1] = sq;
                }
            }
        }
        __syncthreads();
        #pragma unroll
        for (int mt = 0; mt < 4; mt++) {
            #pragma unroll
            for (int rr = 0; rr < 2; rr++) {
                int rl = wr * 64 + mt * 16 + rr * 8 + gr;
                int r  = (bm0 + tile) * 128 + rl;
                float s  = red[rl*8+0] + red[rl*8+2] + red[rl*8+4] + red[rl*8+6];
                float sq = red[rl*8+1] + red[rl*8+3] + red[rl*8+5] + red[rl*8+7];
                float mean = s * (1.0f/Dn);
                float var  = sq * (1.0f/Dn) - mean*mean;
                float rstd = rsqrtf(var + 1e-5f);
                bf16* hrow = hout + (size_t)r * Dn + cbase;
                #pragma unroll
                for (int nt = 0; nt < 8; nt++) {
                    int ci = nt * 8 + 2 * gc;
                    float g0 = lng[cbase + ci], g1 = lng[cbase + ci + 1];
                    float be0 = lnb[cbase + ci], be1 = lnb[cbase + ci + 1];
                    float u0 = (acc[mt][nt][rr*2+0] - mean) * rstd * g0 + be0;
                    float u1 = (acc[mt][nt][rr*2+1] - mean) * rstd * g1 + be1;
                    __nv_bfloat162 bv;
                    bv.x = __float2bfloat16_rn(u0);
                    bv.y = __float2bfloat16_rn(u1);
                    *(__nv_bfloat162*)(hrow + ci) = bv;
                    acc[mt][nt][rr*2+0] = 0.f;
                    acc[mt][nt][rr*2+1] = 0.f;
                }
            }
        }
    };

    const int TOT = TPB * 4;
    for (int g = 0; g < TOT; g++) {
        if (g + 1 < TOT) load_A(g + 1);
        const uint32_t aoff = (uint32_t)(g & 1) * PE_PA_BYTES;
        const uint32_t boff = (uint32_t)(g & 3) * PE_BCH_BYTES;
        ldsm_k(0, aoff, boff, 0);
        #pragma unroll
        for (int kk = 0; kk < 3; kk++) {
            ldsm_k((kk + 1) & 1, aoff, boff, kk + 1);
            mma_all(kk & 1);
        }
        mma_all(1);
        if ((g & 3) == 3) epilogue(g >> 2);      // overlaps in-flight A load
        if (g + 1 < TOT) { CP_WAIT0(); __syncthreads(); }
    }
}

// ---------------- fused build_x + first LN: 1 warp per row ----------------
__global__ void build_ln_kernel(const float* __restrict__ term,
                                const float* __restrict__ pred,
                                const float* __restrict__ gam,
                                const float* __restrict__ bet,
                                float* __restrict__ x, bf16* __restrict__ h) {
    int warp = (blockIdx.x * blockDim.x + threadIdx.x) >> 5;
    int lane = threadIdx.x & 31;
    if (warp >= MROWS) return;
    int s3 = warp % 3;
    int n = warp / 3;
    int t = n / Bn;
    int b = n % Bn;
    const int srcT[3][3] = {{1,2,0},{0,2,1},{1,0,2}};
    const int srcP[3][3] = {{0,2,-1},{0,1,-1},{1,2,-1}};
    const float sgn[3][3] = {{-1.f,-1.f,0.f},{1.f,-1.f,0.f},{1.f,1.f,0.f}};
    int tt = srcT[t][s3];
    int pp = srcP[t][s3];
    float sg = sgn[t][s3];
    const float* trow = term + ((size_t)tt*Bn + b)*Dn + lane*8;
    float4 a0 = *(const float4*)(trow);
    float4 a1 = *(const float4*)(trow + 4);
    float vals[8] = {a0.x,a0.y,a0.z,a0.w,a1.x,a1.y,a1.z,a1.w};
    if (pp >= 0) {
        const float* prow = pred + ((size_t)pp*Bn + b)*Dn + lane*8;
        float4 p0 = *(const float4*)(prow);
        float4 p1 = *(const float4*)(prow + 4);
        float pv[8] = {p0.x,p0.y,p0.z,p0.w,p1.x,p1.y,p1.z,p1.w};
        #pragma unroll
        for (int i = 0; i < 8; i++) vals[i] += sg * pv[i];
    }
    float* xrow = x + (size_t)warp * Dn + lane*8;
    *(float4*)(xrow)     = make_float4(vals[0],vals[1],vals[2],vals[3]);
    *(float4*)(xrow + 4) = make_float4(vals[4],vals[5],vals[6],vals[7]);
    float s = 0.f, sq = 0.f;
    #pragma unroll
    for (int i = 0; i < 8; i++) { s += vals[i]; sq += vals[i]*vals[i]; }
    #pragma unroll
    for (int o = 16; o > 0; o >>= 1) {
        s  += __shfl_xor_sync(0xffffffffu, s,  o);
        sq += __shfl_xor_sync(0xffffffffu, sq, o);
    }
    float mean = s * (1.0f/Dn);
    float var  = sq * (1.0f/Dn) - mean*mean;
    float rstd = rsqrtf(var + 1e-5f);
    float4 g0 = *(const float4*)(gam + lane*8);
    float4 g1 = *(const float4*)(gam + lane*8 + 4);
    float4 b0 = *(const float4*)(bet + lane*8);
    float4 b1 = *(const float4*)(bet + lane*8 + 4);
    float gs[8] = {g0.x,g0.y,g0.z,g0.w,g1.x,g1.y,g1.z,g1.w};
    float bs[8] = {b0.x,b0.y,b0.z,b0.w,b1.x,b1.y,b1.z,b1.w};
    __nv_bfloat162 ov[4];
    #pragma unroll
    for (int i = 0; i < 4; i++) {
        float u0 = (vals[2*i]  -mean)*rstd*gs[2*i]   + bs[2*i];
        float u1 = (vals[2*i+1]-mean)*rstd*gs[2*i+1] + bs[2*i+1];
        ov[i].x = __float2bfloat16_rn(u0);
        ov[i].y = __float2bfloat16_rn(u1);
    }
    *(uint4*)(h + (size_t)warp * Dn + lane*8) = *(uint4*)ov;
}

// ---------------- standalone layernorm: 1 warp per row (fp32 in, bf16 out) ----------------
__global__ void ln_kernel(const float* __restrict__ x,
                          const float* __restrict__ gam,
                          const float* __restrict__ bet,
                          bf16* __restrict__ out) {
    int warp = (blockIdx.x * blockDim.x + threadIdx.x) >> 5;
    int lane = threadIdx.x & 31;
    if (warp >= MROWS) return;
    const float* row = x + (size_t)warp * Dn;
    float4 a0 = *(const float4*)(row + lane*8);
    float4 a1 = *(const float4*)(row + lane*8 + 4);
    float vals[8] = {a0.x,a0.y,a0.z,a0.w,a1.x,a1.y,a1.z,a1.w};
    float s = 0.f, sq = 0.f;
    #pragma unroll
    for (int i = 0; i < 8; i++) { s += vals[i]; sq += vals[i]*vals[i]; }
    #pragma unroll
    for (int o = 16; o > 0; o >>= 1) {
        s  += __shfl_xor_sync(0xffffffffu, s,  o);
        sq += __shfl_xor_sync(0xffffffffu, sq, o);
    }
    float mean = s * (1.0f/Dn);
    float var  = sq * (1.0f/Dn) - mean*mean;
    float rstd = rsqrtf(var + 1e-5f);
    float4 g0 = *(const float4*)(gam + lane*8);
    float4 g1 = *(const float4*)(gam + lane*8 + 4);
    float4 b0 = *(const float4*)(bet + lane*8);
    float4 b1 = *(const float4*)(bet + lane*8 + 4);
    float gs[8] = {g0.x,g0.y,g0.z,g0.w,g1.x,g1.y,g1.z,g1.w};
    float bs[8] = {b0.x,b0.y,b0.z,b0.w,b1.x,b1.y,b1.z,b1.w};
    __nv_bfloat162 ov[4];
    #pragma unroll
    for (int i = 0; i < 4; i++) {
        float u0 = (vals[2*i]  -mean)*rstd*gs[2*i]   + bs[2*i];
        float u1 = (vals[2*i+1]-mean)*rstd*gs[2*i+1] + bs[2*i+1];
        ov[i].x = __float2bfloat16_rn(u0);
        ov[i].y = __float2bfloat16_rn(u1);
    }
    *(uint4*)(out + (size_t)warp * Dn + lane*8) = *(uint4*)ov;
}

// ---------------- attention on fused qkv buffer (bf16): 1 warp per (n, head) ----------------
__global__ void attn_kernel(const bf16* __restrict__ qkv, bf16* __restrict__ o) {
    int widx = (blockIdx.x * blockDim.x + threadIdx.x) >> 5;
    int lane = threadIdx.x & 31;
    if (widx >= NG * Hn) return;
    int n = widx >> 3;
    int h = widx & 7;
    size_t rb = (size_t)n * 3 * (3*Dn) + h*DHn + lane;
    float qs[3], ks[3], vs[3];
    #pragma unroll
    for (int s = 0; s < 3; s++) {
        qs[s] = __bfloat162float(qkv[rb + (size_t)s*(3*Dn)]);
        ks[s] = __bfloat162float(qkv[rb + (size_t)s*(3*Dn) + Dn]);
        vs[s] = __bfloat162float(qkv[rb + (size_t)s*(3*Dn) + 2*Dn]);
    }
    float sc[3][3];
    #pragma unroll
    for (int s = 0; s < 3; s++)
        #pragma unroll
        for (int t = 0; t < 3; t++) {
            float p = qs[s]*ks[t];
            #pragma unroll
            for (int off = 16; off > 0; off >>= 1)
                p += __shfl_xor_sync(0xffffffffu, p, off);
            sc[s][t] = p * SCALE_F;
        }
    #pragma unroll
    for (int s = 0; s < 3; s++) {
        float m = fmaxf(sc[s][0], fmaxf(sc[s][1], sc[s][2]));
        float e0 = __expf(sc[s][0]-m);
        float e1 = __expf(sc[s][1]-m);
        float e2 = __expf(sc[s][2]-m);
        float inv = 1.0f/(e0+e1+e2);
        float os = (e0*vs[0] + e1*vs[1] + e2*vs[2]) * inv;
        o[(size_t)(n*3+s)*Dn + h*DHn + lane] = __float2bfloat16_rn(os);
    }
}

// ---------------- one-shot transpose+convert of all weights (both layers) ----------------
__global__ void transpose_all(const float* __restrict__ Wq, const float* __restrict__ Wk,
                              const float* __restrict__ Wv, const float* __restrict__ Wo,
                              const float* __restrict__ W1, const float* __restrict__ W2,
                              bf16* __restrict__ wt) {
    __shared__ float t[32][33];
    int bid = blockIdx.x;
    int l = bid / 768;
    int tt = bid % 768;
    const float* in; bf16* out; int N, n0, k0, outld;
    if (tt < 192) {
        int which = tt / 64; int q = tt % 64;
        const float* Ws[3] = {Wq, Wk, Wv};
        in = Ws[which] + (size_t)l*Dn*Dn;
        out = wt + (size_t)l*WT_LAYER + which*Dn*Dn;
        N = Dn; outld = Dn;
        n0 = (q & 7) * 32; k0 = (q >> 3) * 32;
    } else if (tt < 256) {
        int q = tt - 192;
        in = Wo + (size_t)l*Dn*Dn;
        out = wt + (size_t)l*WT_LAYER + 196608;
        N = Dn; outld = Dn;
        n0 = (q & 7) * 32; k0 = (q >> 3) * 32;
    } else if (tt < 512) {
        int q = tt - 256;
        in = W1 + (size_t)l*Dn*FFn;
        out = wt + (size_t)l*WT_LAYER + 262144;
        N = FFn; outld = Dn;
        n0 = (q & 31) * 32; k0 = (q >> 5) * 32;
    } else {
        int q = tt - 512;
        in = W2 + (size_t)l*FFn*Dn;
        out = wt + (size_t)l*WT_LAYER + 524288;
        N = Dn; outld = FFn;
        n0 = (q & 7) * 32; k0 = (q >> 3) * 32;
    }
    int tx = threadIdx.x, ty = threadIdx.y;   // 32 x 8
    #pragma unroll
    for (int i = ty; i < 32; i += 8)
        t[i][tx] = in[(size_t)(k0+i)*N + n0+tx];
    __syncthreads();
    #pragma unroll
    for (int i = ty; i < 32; i += 8)
        out[(size_t)(n0+i)*outld + k0+tx] = __float2bfloat16_rn(t[tx][i]);
}

__global__ void concat_bias_kernel(const float* __restrict__ bq, const float* __restrict__ bk,
                                   const float* __restrict__ bv, float* __restrict__ out) {
    int i = blockIdx.x*blockDim.x + threadIdx.x;
    if (i >= 2*3*Dn) return;
    int l = i / (3*Dn);
    int j = i % (3*Dn);
    float v;
    if (j < Dn)        v = bq[l*Dn + j];
    else if (j < 2*Dn) v = bk[l*Dn + j-Dn];
    else               v = bv[l*Dn + j-2*Dn];
    out[i] = v;
}

// ---------------- fused final LN + mean-pool: 1 warp per group ----------------
__global__ void ln_mean_kernel(const float* __restrict__ x,
                               const float* __restrict__ gam,
                               const float* __restrict__ bet,
                               float* __restrict__ out) {
    int warp = (blockIdx.x * blockDim.x + threadIdx.x) >> 5;
    int lane = threadIdx.x & 31;
    if (warp >= NG) return;
    float4 g0 = *(const float4*)(gam + lane*8);
    float4 g1 = *(const float4*)(gam + lane*8 + 4);
    float4 b0 = *(const float4*)(bet + lane*8);
    float4 b1 = *(const float4*)(bet + lane*8 + 4);
    float gs[8] = {g0.x,g0.y,g0.z,g0.w,g1.x,g1.y,g1.z,g1.w};
    float bs[8] = {b0.x,b0.y,b0.z,b0.w,b1.x,b1.y,b1.z,b1.w};
    float avg[8] = {0,0,0,0,0,0,0,0};
    #pragma unroll
    for (int s3 = 0; s3 < 3; s3++) {
        const float* row = x + ((size_t)warp*3 + s3) * Dn;
        float4 a0 = *(const float4*)(row + lane*8);
        float4 a1 = *(const float4*)(row + lane*8 + 4);
        float vals[8] = {a0.x,a0.y,a0.z,a0.w,a1.x,a1.y,a1.z,a1.w};
        float s = 0.f, sq = 0.f;
        #pragma unroll
        for (int i = 0; i < 8; i++) { s += vals[i]; sq += vals[i]*vals[i]; }
        #pragma unroll
        for (int o = 16; o > 0; o >>= 1) {
            s  += __shfl_xor_sync(0xffffffffu, s,  o);
            sq += __shfl_xor_sync(0xffffffffu, sq, o);
        }
        float mean = s * (1.0f/Dn);
        float var  = sq * (1.0f/Dn) - mean*mean;
        float rstd = rsqrtf(var + 1e-5f);
        #pragma unroll
        for (int i = 0; i < 8; i++)
            avg[i] += ((vals[i]-mean)*rstd*gs[i] + bs[i]) * (1.0f/3.0f);
    }
    float* orow = out + (size_t)warp * Dn;
    *(float4*)(orow + lane*8)     = make_float4(avg[0],avg[1],avg[2],avg[3]);
    *(float4*)(orow + lane*8 + 4) = make_float4(avg[4],avg[5],avg[6],avg[7]);
}

// ---------------- host ----------------
extern "C" void kernel_launch(void* const* d_in, const int* in_sizes, int n_in,
                              void* d_out, int out_size) {
    const float* term  = (const float*)d_in[0];
    const float* pred  = (const float*)d_in[1];
    const float* Wq    = (const float*)d_in[2];
    const float* Wk    = (const float*)d_in[3];
    const float* Wv    = (const float*)d_in[4];
    const float* Wo    = (const float*)d_in[5];
    const float* bq    = (const float*)d_in[6];
    const float* bk    = (const float*)d_in[7];
    const float* bv    = (const float*)d_in[8];
    const float* bo    = (const float*)d_in[9];
    const float* ln1g  = (const float*)d_in[10];
    const float* ln1b  = (const float*)d_in[11];
    const float* ln2g  = (const float*)d_in[12];
    const float* ln2b  = (const float*)d_in[13];
    const float* W1    = (const float*)d_in[14];
    const float* b1    = (const float*)d_in[15];
    const float* W2    = (const float*)d_in[16];
    const float* b2    = (const float*)d_in[17];
    const float* lnfg  = (const float*)d_in[18];
    const float* lnfb  = (const float*)d_in[19];
    float* out = (float*)d_out;

    float *x, *bqkv;
    bf16 *h, *qkv, *o, *f, *wt;
    cudaGetSymbolAddress((void**)&x,   g_x);
    cudaGetSymbolAddress((void**)&h,   g_h);
    cudaGetSymbolAddress((void**)&qkv, g_qkv);
    cudaGetSymbolAddress((void**)&o,   g_o);
    cudaGetSymbolAddress((void**)&f,   g_f);
    cudaGetSymbolAddress((void**)&wt,  g_wt);
    cudaGetSymbolAddress((void**)&bqkv,g_bqkv);

    cudaFuncSetAttribute(gemm_tc_sm<0,false,true >, cudaFuncAttributeMaxDynamicSharedMemorySize, SM_SMEM_BYTES);
    cudaFuncSetAttribute(gemm_tc_sm<1,false,true >, cudaFuncAttributeMaxDynamicSharedMemorySize, SM_SMEM_BYTES);
    cudaFuncSetAttribute(gemm_tc_sm<0,true ,false>, cudaFuncAttributeMaxDynamicSharedMemorySize, SM_SMEM_BYTES);
    cudaFuncSetAttribute(gemm_tc_pe, cudaFuncAttributeMaxDynamicSharedMemorySize, PE_SMEM_BYTES);

    // weight prep + fused build_x + LN1(layer0)
    transpose_all<<<2*768, dim3(32,8)>>>(Wq, Wk, Wv, Wo, W1, W2, wt);
    concat_bias_kernel<<<6, 256>>>(bq, bk, bv, bqkv);
    build_ln_kernel<<<MROWS/8, 256>>>(term, pred, ln1g, ln1b, x, h);

    const int MB  = MROWS / 128;        // 1152
    const int MBP = MB / TPB;           // 288
    for (int l = 0; l < NLn; l++) {
        const bf16* wl = wt + (size_t)l*WT_LAYER;

        // fused QKV GEMM (small kernel, 2 CTAs/SM): [MROWS,256] @ [256,768]
        gemm_tc_sm<0,false,true><<<dim3(6, MB), 128, SM_SMEM_BYTES>>>(
            h, Dn, wl, bqkv + l*3*Dn, nullptr, qkv, 3*Dn, Dn);

        // attention
        attn_kernel<<<NG*Hn/8, 256>>>(qkv, o);

        // output projection + residual + fused LN2 (persistent-B EPILN, TPB m-tiles)
        gemm_tc_pe<<<dim3(1, MBP), 256, PE_SMEM_BYTES>>>(
            o, Dn, wl + 196608, bo + l*Dn, x, x, Dn,
            ln2g + l*Dn, ln2b + l*Dn, h);

        // FFN up (relu, small kernel): [MROWS,256] @ [256,1024]
        gemm_tc_sm<1,false,true><<<dim3(8, MB), 128, SM_SMEM_BYTES>>>(
            h, Dn, wl + 262144, b1 + l*FFn, nullptr, f, FFn, Dn);

        // FFN down + residual -> x fp32 (small kernel, 2 CTAs/SM)
        gemm_tc_sm<0,true,false><<<dim3(2, MB), 128, SM_SMEM_BYTES>>>(
            f, FFn, wl + 524288, b2 + l*Dn, x, x, Dn, FFn);

        // LN1 of next layer (standalone)
        if (l + 1 < NLn)
            ln_kernel<<<MROWS/8, 256>>>(x, ln1g + (l+1)*Dn, ln1b + (l+1)*Dn, h);
    }

    // fused final LN + mean pool
    ln_mean_kernel<<<NG/8, 256>>>(x, lnfg, lnfb, out);
    (void)in_sizes; (void)n_in; (void)out_size;
}

// round 17
// speedup vs baseline: 1.1230x; 1.0531x over previous
#include <cuda_runtime.h>
#include <cuda_bf16.h>
#include <cstdint>
#include <math.h>

// Problem constants
#define Tn   3
#define Bn   16384
#define Dn   256
#define Hn   8
#define DHn  32
#define NLn  2
#define FFn  1024
#define NG   (Tn*Bn)        // 49152 row-groups
#define MROWS (NG*3)        // 147456 total rows
#define SCALE_F 0.17677669529663687f   // 1/sqrt(32)

typedef __nv_bfloat16 bf16;

// ---------------- device scratch (allocation-free) ----------------
__device__ float g_x[MROWS*Dn];                 // residual stream (fp32)
__device__ bf16  g_h[MROWS*Dn];                 // LN output (bf16)
__device__ bf16  g_qkv[(size_t)MROWS*3*Dn];     // fused QKV output (bf16)
__device__ bf16  g_o[MROWS*Dn];                 // attention output (bf16)
__device__ bf16  g_f[(size_t)MROWS*FFn];        // FFN intermediate (bf16)
#define WT_LAYER 786432
__device__ bf16  g_wt[2*WT_LAYER];
__device__ float g_bqkv[2*3*Dn];                // concatenated qkv bias, both layers

// =================== helpers ===================
__device__ __forceinline__ uint32_t smem_u32(const void* p) {
    uint32_t a;
    asm("{ .reg .u64 t; cvta.to.shared.u64 t, %1; cvt.u32.u64 %0, t; }" : "=r"(a) : "l"(p));
    return a;
}
#define CP_ASYNC16(dst, src) \
    asm volatile("cp.async.cg.shared.global [%0], [%1], 16;" :: "r"(dst), "l"(src) : "memory")
#define CP_COMMIT() asm volatile("cp.async.commit_group;" ::: "memory")
#define CP_WAIT0()  asm volatile("cp.async.wait_group 0;" ::: "memory")
#define CP_WAIT1()  asm volatile("cp.async.wait_group 1;" ::: "memory")

#define LDSM_X4(r0, r1, r2, r3, addr) \
    asm volatile("ldmatrix.sync.aligned.m8n8.x4.shared.b16 {%0,%1,%2,%3}, [%4];" \
        : "=r"(r0), "=r"(r1), "=r"(r2), "=r"(r3) : "r"(addr))

// mma.sync m16n8k16 bf16
__device__ __forceinline__ void mma_bf16(float* c, const uint32_t* a, const uint32_t* b) {
    asm volatile(
        "mma.sync.aligned.m16n8k16.row.col.f32.bf16.bf16.f32 "
        "{%0,%1,%2,%3}, {%4,%5,%6,%7}, {%8,%9}, {%0,%1,%2,%3};"
        : "+f"(c[0]), "+f"(c[1]), "+f"(c[2]), "+f"(c[3])
        : "r"(a[0]), "r"(a[1]), "r"(a[2]), "r"(a[3]), "r"(b[0]), "r"(b[1]));
}

#define KC   64
#define LDSB 72
#define NSTG 3

// ======== SMALL kernel (R13): 128x128 tile, 128 thr, 2 CTAs/SM — QKV, FF1, FF2 ========
static constexpr int TILE_A_SM = 128 * LDSB;               // 9216
static constexpr int TILE_B_SM = 128 * LDSB;               // 9216
static constexpr int STAGE_SM  = TILE_A_SM + TILE_B_SM;    // 18432 bf16
static constexpr int STAGE_SM_BYTES = STAGE_SM * 2;        // 36864
static constexpr int SM_SMEM_BYTES = NSTG * STAGE_SM_BYTES; // 110592

template<int ACT, bool RESID, bool OBF>
__global__ __launch_bounds__(128, 2)
void gemm_tc_sm(const bf16* __restrict__ A, int lda,
                const bf16* __restrict__ Bt,
                const float* __restrict__ bias,
                const float* __restrict__ resid,
                void* __restrict__ Cv, int ldc, int K) {
    extern __shared__ bf16 smem[];
    const uint32_t sbase = smem_u32(smem);
    const int tid = threadIdx.x;
    const int wid = tid >> 5, lane = tid & 31;
    const int wr = wid >> 1, wn = wid & 1;      // 2x2 warp grid, 64x64 warp tiles
    const int gr = lane >> 2, gc = lane & 3;
    const int bm = blockIdx.y, bn = blockIdx.x;

    const bf16* Ag0 = A  + (size_t)bm * 128 * lda;
    const bf16* Bg0 = Bt + (size_t)bn * 128 * K;
    const int NC = K / KC;

    float acc[4][8][4];
    #pragma unroll
    for (int mt = 0; mt < 4; mt++)
        #pragma unroll
        for (int nt = 0; nt < 8; nt++)
            #pragma unroll
            for (int i = 0; i < 4; i++) acc[mt][nt][i] = 0.f;

    uint32_t aAddr[4], bAddr[4];
    {
        int arow = (lane & 15);
        int acol = (lane >> 4) * 8;
        #pragma unroll
        for (int mt = 0; mt < 4; mt++) {
            int r = wr*64 + mt*16 + arow;
            aAddr[mt] = sbase + (uint32_t)(r * LDSB + acol) * 2;
        }
        int brow = ((lane >> 4) * 8) + (lane & 7);
        int bcol = ((lane >> 3) & 1) * 8;
        #pragma unroll
        for (int p = 0; p < 4; p++) {
            int r = wn*64 + p*16 + brow;
            bAddr[p] = sbase + (uint32_t)(TILE_A_SM + r * LDSB + bcol) * 2;
        }
    }

    auto load_chunk = [&](int kc, int s) {
        bf16* As = smem + s * STAGE_SM;
        bf16* Bs = As + TILE_A_SM;
        const bf16* Agc = Ag0 + kc * KC;
        const bf16* Bgc = Bg0 + kc * KC;
        #pragma unroll
        for (int j = 0; j < 8; j++) {
            int slot = tid + 128 * j;
            int row  = slot >> 3, c8 = slot & 7;
            uint32_t da = smem_u32(As + row * LDSB + c8 * 8);
            CP_ASYNC16(da, Agc + (size_t)row * lda + c8 * 8);
            uint32_t db = smem_u32(Bs + row * LDSB + c8 * 8);
            CP_ASYNC16(db, Bgc + (size_t)row * K + c8 * 8);
        }
        CP_COMMIT();
    };

    uint32_t fa[2][4][4], fb[2][4][4];
    auto ldsm_all = [&](int buf, uint32_t ko) {
        #pragma unroll
        for (int mt = 0; mt < 4; mt++)
            LDSM_X4(fa[buf][mt][0], fa[buf][mt][1], fa[buf][mt][2], fa[buf][mt][3],
                    aAddr[mt] + ko);
        #pragma unroll
        for (int p = 0; p < 4; p++)
            LDSM_X4(fb[buf][p][0], fb[buf][p][1], fb[buf][p][2], fb[buf][p][3],
                    bAddr[p] + ko);
    };
    auto mma_all = [&](int buf) {
        #pragma unroll
        for (int mt = 0; mt < 4; mt++)
            #pragma unroll
            for (int nt = 0; nt < 8; nt++)
                mma_bf16(acc[mt][nt], fa[buf][mt], &fb[buf][nt >> 1][(nt & 1) * 2]);
    };

    load_chunk(0, 0);
    if (NC > 1) { load_chunk(1, 1); CP_WAIT1(); } else { CP_WAIT0(); }
    __syncthreads();
    ldsm_all(0, 0);

    int stg = 0;
    for (int i = 0; i < NC; i++) {
        if (i + 2 < NC) load_chunk(i + 2, (stg + 2) % NSTG);
        const uint32_t soff = stg * STAGE_SM_BYTES;
        #pragma unroll
        for (int kk = 0; kk < 3; kk++) {
            ldsm_all((kk + 1) & 1, soff + (kk + 1) * 32);
            mma_all(kk & 1);
        }
        if (i + 1 < NC) {
            if (i + 2 < NC) CP_WAIT1(); else CP_WAIT0();
            __syncthreads();
            ldsm_all(0, ((stg + 1) % NSTG) * STAGE_SM_BYTES);
            mma_all(1);
        } else {
            mma_all(1);
        }
        stg = (stg + 1) % NSTG;
    }

    const int cbase = bn * 128 + wn * 64;
    #pragma unroll
    for (int mt = 0; mt < 4; mt++) {
        #pragma unroll
        for (int rr = 0; rr < 2; rr++) {
            int r = bm * 128 + wr * 64 + mt * 16 + gr + rr * 8;
            const float* rrow = RESID ? (resid + (size_t)r * ldc + cbase) : nullptr;
            #pragma unroll
            for (int nt = 0; nt < 8; nt++) {
                int ci = nt * 8 + 2 * gc;
                float v0 = acc[mt][nt][rr*2 + 0] + bias[cbase + ci];
                float v1 = acc[mt][nt][rr*2 + 1] + bias[cbase + ci + 1];
                if (RESID) {
                    float2 rv = *(const float2*)(rrow + ci);
                    v0 += rv.x; v1 += rv.y;
                }
                if (ACT == 1) { v0 = fmaxf(v0, 0.f); v1 = fmaxf(v1, 0.f); }
                if (OBF) {
                    bf16* crow = (bf16*)Cv + (size_t)r * ldc + cbase;
                    __nv_bfloat162 bv;
                    bv.x = __float2bfloat16_rn(v0);
                    bv.y = __float2bfloat16_rn(v1);
                    *(__nv_bfloat162*)(crow + ci) = bv;
                } else {
                    float* crow = (float*)Cv + (size_t)r * ldc + cbase;
                    *(float2*)(crow + ci) = make_float2(v0, v1);
                }
            }
        }
    }
}

// ======== PERSISTENT-B EPILN kernel: proj (K=256, N=256), 256 thr, TPB m-tiles ========
#define TPB 4
static constexpr int PE_BCH_BF    = 256 * LDSB;             // bf16 per B chunk
static constexpr int PE_BCH_BYTES = PE_BCH_BF * 2;          // 36864
static constexpr int PE_PB_BYTES  = 4 * PE_BCH_BYTES;       // 147456
static constexpr int PE_PA_BF     = 128 * LDSB;
static constexpr int PE_PA_BYTES  = PE_PA_BF * 2;           // 18432
static constexpr int PE_RED_BYTES = 128 * 8 * 4;            // 4096
static constexpr int PE_SMEM_BYTES = PE_PB_BYTES + 2*PE_PA_BYTES + PE_RED_BYTES; // 188416

__global__ __launch_bounds__(256)
void gemm_tc_pe(const bf16* __restrict__ A, int lda,
                const bf16* __restrict__ Bt,
                const float* __restrict__ bias,
                const float* __restrict__ resid,
                float* __restrict__ Cx, int ldc,
                const float* __restrict__ lng, const float* __restrict__ lnb,
                bf16* __restrict__ hout) {
    extern __shared__ bf16 smem[];
    const uint32_t sbase = smem_u32(smem);
    const int tid = threadIdx.x;
    const int wid = tid >> 5, lane = tid & 31;
    const int wr = wid >> 2, wn = wid & 3;      // 2x4 warp grid, 64x64 warp tiles
    const int gr = lane >> 2, gc = lane & 3;
    const int bm0 = blockIdx.y * TPB;

    float acc[4][8][4];
    #pragma unroll
    for (int mt = 0; mt < 4; mt++)
        #pragma unroll
        for (int nt = 0; nt < 8; nt++)
            #pragma unroll
            for (int i = 0; i < 4; i++) acc[mt][nt][i] = 0.f;

    uint32_t aAddr[4], bAddr[4];
    {
        int arow = (lane & 15);
        int acol = (lane >> 4) * 8;
        #pragma unroll
        for (int mt = 0; mt < 4; mt++) {
            int r = wr*64 + mt*16 + arow;
            aAddr[mt] = sbase + PE_PB_BYTES + (uint32_t)(r * LDSB + acol) * 2;
        }
        int brow = ((lane >> 4) * 8) + (lane & 7);
        int bcol = ((lane >> 3) & 1) * 8;
        #pragma unroll
        for (int p = 0; p < 4; p++) {
            int r = wn*64 + p*16 + brow;
            bAddr[p] = sbase + (uint32_t)(r * LDSB + bcol) * 2;
        }
    }

    auto load_A = [&](int g) {   // g: tile = g>>2, kc = g&3, stage = g&1
        int tile = g >> 2, kc = g & 3, st = g & 1;
        bf16* As = smem + PE_PB_BYTES/2 + st * PE_PA_BF;
        const bf16* Agc = A + (size_t)(bm0 + tile) * 128 * lda + kc * KC;
        #pragma unroll
        for (int j = 0; j < 4; j++) {
            int slot = tid + 256 * j;            // 1024 slots
            int row  = slot >> 3, c8 = slot & 7;
            uint32_t da = smem_u32(As + row * LDSB + c8 * 8);
            CP_ASYNC16(da, Agc + (size_t)row * lda + c8 * 8);
        }
        CP_COMMIT();
    };

    // prologue: all 4 B chunks (256 rows each) + A chunk 0
    {
        #pragma unroll
        for (int c = 0; c < 4; c++) {
            bf16* Bs = smem + c * PE_BCH_BF;
            const bf16* Bgc = Bt + c * KC;
            #pragma unroll
            for (int j = 0; j < 8; j++) {
                int slot = tid + 256 * j;        // 2048 slots per chunk
                int row  = slot >> 3, c8 = slot & 7;
                uint32_t db = smem_u32(Bs + row * LDSB + c8 * 8);
                CP_ASYNC16(db, Bgc + (size_t)row * 256 + c8 * 8);
            }
        }
        bf16* As = smem + PE_PB_BYTES/2;
        const bf16* Agc = A + (size_t)bm0 * 128 * lda;
        #pragma unroll
        for (int j = 0; j < 4; j++) {
            int slot = tid + 256 * j;
            int row  = slot >> 3, c8 = slot & 7;
            uint32_t da = smem_u32(As + row * LDSB + c8 * 8);
            CP_ASYNC16(da, Agc + (size_t)row * lda + c8 * 8);
        }
        CP_COMMIT();
        CP_WAIT0();
        __syncthreads();
    }

    uint32_t fa[2][4][4], fb[2][4][4];
    auto ldsm_k = [&](int buf, uint32_t aoff, uint32_t boff, int kk) {
        const uint32_t ko = (uint32_t)kk * 32;
        #pragma unroll
        for (int mt = 0; mt < 4; mt++)
            LDSM_X4(fa[buf][mt][0], fa[buf][mt][1], fa[buf][mt][2], fa[buf][mt][3],
                    aAddr[mt] + aoff + ko);
        #pragma unroll
        for (int p = 0; p < 4; p++)
            LDSM_X4(fb[buf][p][0], fb[buf][p][1], fb[buf][p][2], fb[buf][p][3],
                    bAddr[p] + boff + ko);
    };
    auto mma_all = [&](int buf) {
        #pragma unroll
        for (int mt = 0; mt < 4; mt++)
            #pragma unroll
            for (int nt = 0; nt < 8; nt++)
                mma_bf16(acc[mt][nt], fa[buf][mt], &fb[buf][nt >> 1][(nt & 1) * 2]);
    };

    float* red = (float*)(smem + (PE_PB_BYTES + 2*PE_PA_BYTES)/2);
    auto epilogue = [&](int tile) {
        const int cbase = wn * 64;
        __syncthreads();
        #pragma unroll
        for (int mt = 0; mt < 4; mt++) {
            #pragma unroll
            for (int rr = 0; rr < 2; rr++) {
                int rl = wr * 64 + mt * 16 + rr * 8 + gr;
                int r  = (bm0 + tile) * 128 + rl;
                const float* rrow = resid + (size_t)r * ldc + cbase;
                float* crow = Cx + (size_t)r * ldc + cbase;
                float s = 0.f, sq = 0.f;
                #pragma unroll
                for (int nt = 0; nt < 8; nt++) {
                    int ci = nt * 8 + 2 * gc;
                    float2 rv = *(const float2*)(rrow + ci);
                    float v0 = acc[mt][nt][rr*2 + 0] + bias[cbase + ci]     + rv.x;
                    float v1 = acc[mt][nt][rr*2 + 1] + bias[cbase + ci + 1] + rv.y;
                    acc[mt][nt][rr*2 + 0] = v0;
                    acc[mt][nt][rr*2 + 1] = v1;
                    *(float2*)(crow + ci) = make_float2(v0, v1);
                    s += v0 + v1; sq += v0*v0 + v1*v1;
                }
                s  += __shfl_xor_sync(0xffffffffu, s, 1);
                sq += __shfl_xor_sync(0xffffffffu, sq, 1);
                s  += __shfl_xor_sync(0xffffffffu, s, 2);
                sq += __shfl_xor_sync(0xffffffffu, sq, 2);
                if (gc == 0) {
                    red[rl * 8 + wn * 2 + 0] = s;
                    red[rl * 8 + wn * 2 + 1] = sq;
                }
            }
        }
        __syncthreads();
        #pragma unroll
        for (int mt = 0; mt < 4; mt++) {
            #pragma unroll
            for (int rr = 0; rr < 2; rr++) {
                int rl = wr * 64 + mt * 16 + rr * 8 + gr;
                int r  = (bm0 + tile) * 128 + rl;
                float s  = red[rl*8+0] + red[rl*8+2] + red[rl*8+4] + red[rl*8+6];
                float sq = red[rl*8+1] + red[rl*8+3] + red[rl*8+5] + red[rl*8+7];
                float mean = s * (1.0f/Dn);
                float var  = sq * (1.0f/Dn) - mean*mean;
                float rstd = rsqrtf(var + 1e-5f);
                bf16* hrow = hout + (size_t)r * Dn + cbase;
                #pragma unroll
                for (int nt = 0; nt < 8; nt++) {
                    int ci = nt * 8 + 2 * gc;
                    float g0 = lng[cbase + ci], g1 = lng[cbase + ci + 1];
                    float be0 = lnb[cbase + ci], be1 = lnb[cbase + ci + 1];
                    float u0 = (acc[mt][nt][rr*2+0] - mean) * rstd * g0 + be0;
                    float u1 = (acc[mt][nt][rr*2+1] - mean) * rstd * g1 + be1;
                    __nv_bfloat162 bv;
                    bv.x = __float2bfloat16_rn(u0);
                    bv.y = __float2bfloat16_rn(u1);
                    *(__nv_bfloat162*)(hrow + ci) = bv;
                    acc[mt][nt][rr*2+0] = 0.f;
                    acc[mt][nt][rr*2+1] = 0.f;
                }
            }
        }
    };

    const int TOT = TPB * 4;
    for (int g = 0; g < TOT; g++) {
        if (g + 1 < TOT) load_A(g + 1);
        const uint32_t aoff = (uint32_t)(g & 1) * PE_PA_BYTES;
        const uint32_t boff = (uint32_t)(g & 3) * PE_BCH_BYTES;
        ldsm_k(0, aoff, boff, 0);
        #pragma unroll
        for (int kk = 0; kk < 3; kk++) {
            ldsm_k((kk + 1) & 1, aoff, boff, kk + 1);
            mma_all(kk & 1);
        }
        mma_all(1);
        if ((g & 3) == 3) epilogue(g >> 2);
        if (g + 1 < TOT) { CP_WAIT0(); __syncthreads(); }
    }
}

// ---------------- fused build_x + first LN: 1 warp per row ----------------
__global__ void build_ln_kernel(const float* __restrict__ term,
                                const float* __restrict__ pred,
                                const float* __restrict__ gam,
                                const float* __restrict__ bet,
                                float* __restrict__ x, bf16* __restrict__ h) {
    int warp = (blockIdx.x * blockDim.x + threadIdx.x) >> 5;
    int lane = threadIdx.x & 31;
    if (warp >= MROWS) return;
    int s3 = warp % 3;
    int n = warp / 3;
    int t = n / Bn;
    int b = n % Bn;
    const int srcT[3][3] = {{1,2,0},{0,2,1},{1,0,2}};
    const int srcP[3][3] = {{0,2,-1},{0,1,-1},{1,2,-1}};
    const float sgn[3][3] = {{-1.f,-1.f,0.f},{1.f,-1.f,0.f},{1.f,1.f,0.f}};
    int tt = srcT[t][s3];
    int pp = srcP[t][s3];
    float sg = sgn[t][s3];
    const float* trow = term + ((size_t)tt*Bn + b)*Dn + lane*8;
    float4 a0 = *(const float4*)(trow);
    float4 a1 = *(const float4*)(trow + 4);
    float vals[8] = {a0.x,a0.y,a0.z,a0.w,a1.x,a1.y,a1.z,a1.w};
    if (pp >= 0) {
        const float* prow = pred + ((size_t)pp*Bn + b)*Dn + lane*8;
        float4 p0 = *(const float4*)(prow);
        float4 p1 = *(const float4*)(prow + 4);
        float pv[8] = {p0.x,p0.y,p0.z,p0.w,p1.x,p1.y,p1.z,p1.w};
        #pragma unroll
        for (int i = 0; i < 8; i++) vals[i] += sg * pv[i];
    }
    float* xrow = x + (size_t)warp * Dn + lane*8;
    *(float4*)(xrow)     = make_float4(vals[0],vals[1],vals[2],vals[3]);
    *(float4*)(xrow + 4) = make_float4(vals[4],vals[5],vals[6],vals[7]);
    float s = 0.f, sq = 0.f;
    #pragma unroll
    for (int i = 0; i < 8; i++) { s += vals[i]; sq += vals[i]*vals[i]; }
    #pragma unroll
    for (int o = 16; o > 0; o >>= 1) {
        s  += __shfl_xor_sync(0xffffffffu, s,  o);
        sq += __shfl_xor_sync(0xffffffffu, sq, o);
    }
    float mean = s * (1.0f/Dn);
    float var  = sq * (1.0f/Dn) - mean*mean;
    float rstd = rsqrtf(var + 1e-5f);
    float4 g0 = *(const float4*)(gam + lane*8);
    float4 g1 = *(const float4*)(gam + lane*8 + 4);
    float4 b0 = *(const float4*)(bet + lane*8);
    float4 b1 = *(const float4*)(bet + lane*8 + 4);
    float gs[8] = {g0.x,g0.y,g0.z,g0.w,g1.x,g1.y,g1.z,g1.w};
    float bs[8] = {b0.x,b0.y,b0.z,b0.w,b1.x,b1.y,b1.z,b1.w};
    __nv_bfloat162 ov[4];
    #pragma unroll
    for (int i = 0; i < 4; i++) {
        float u0 = (vals[2*i]  -mean)*rstd*gs[2*i]   + bs[2*i];
        float u1 = (vals[2*i+1]-mean)*rstd*gs[2*i+1] + bs[2*i+1];
        ov[i].x = __float2bfloat16_rn(u0);
        ov[i].y = __float2bfloat16_rn(u1);
    }
    *(uint4*)(h + (size_t)warp * Dn + lane*8) = *(uint4*)ov;
}

// ---------------- standalone layernorm: 1 warp per row (fp32 in, bf16 out) ----------------
__global__ void ln_kernel(const float* __restrict__ x,
                          const float* __restrict__ gam,
                          const float* __restrict__ bet,
                          bf16* __restrict__ out) {
    int warp = (blockIdx.x * blockDim.x + threadIdx.x) >> 5;
    int lane = threadIdx.x & 31;
    if (warp >= MROWS) return;
    const float* row = x + (size_t)warp * Dn;
    float4 a0 = *(const float4*)(row + lane*8);
    float4 a1 = *(const float4*)(row + lane*8 + 4);
    float vals[8] = {a0.x,a0.y,a0.z,a0.w,a1.x,a1.y,a1.z,a1.w};
    float s = 0.f, sq = 0.f;
    #pragma unroll
    for (int i = 0; i < 8; i++) { s += vals[i]; sq += vals[i]*vals[i]; }
    #pragma unroll
    for (int o = 16; o > 0; o >>= 1) {
        s  += __shfl_xor_sync(0xffffffffu, s,  o);
        sq += __shfl_xor_sync(0xffffffffu, sq, o);
    }
    float mean = s * (1.0f/Dn);
    float var  = sq * (1.0f/Dn) - mean*mean;
    float rstd = rsqrtf(var + 1e-5f);
    float4 g0 = *(const float4*)(gam + lane*8);
    float4 g1 = *(const float4*)(gam + lane*8 + 4);
    float4 b0 = *(const float4*)(bet + lane*8);
    float4 b1 = *(const float4*)(bet + lane*8 + 4);
    float gs[8] = {g0.x,g0.y,g0.z,g0.w,g1.x,g1.y,g1.z,g1.w};
    float bs[8] = {b0.x,b0.y,b0.z,b0.w,b1.x,b1.y,b1.z,b1.w};
    __nv_bfloat162 ov[4];
    #pragma unroll
    for (int i = 0; i < 4; i++) {
        float u0 = (vals[2*i]  -mean)*rstd*gs[2*i]   + bs[2*i];
        float u1 = (vals[2*i+1]-mean)*rstd*gs[2*i+1] + bs[2*i+1];
        ov[i].x = __float2bfloat16_rn(u0);
        ov[i].y = __float2bfloat16_rn(u1);
    }
    *(uint4*)(out + (size_t)warp * Dn + lane*8) = *(uint4*)ov;
}

// ---------------- attention v2: 1 warp per (n, head-pair); bf162 loads ----------------
// half = lane>>4 selects head within pair; 16 lanes x bf162 cover the 32 head dims.
__global__ void attn_kernel(const bf16* __restrict__ qkv, bf16* __restrict__ o) {
    int widx = (blockIdx.x * blockDim.x + threadIdx.x) >> 5;
    int lane = threadIdx.x & 31;
    if (widx >= NG * (Hn/2)) return;
    int n  = widx >> 2;
    int hp = widx & 3;
    int half = lane >> 4;           // 0 or 1 -> head hp*2 + half
    int l16  = lane & 15;
    int h = hp * 2 + half;
    size_t rb = (size_t)n * 3 * (3*Dn) + h*DHn + 2*l16;

    float q0[3], q1[3], k0[3], k1[3], v0[3], v1[3];
    #pragma unroll
    for (int s = 0; s < 3; s++) {
        __nv_bfloat162 qv = *(const __nv_bfloat162*)(qkv + rb + (size_t)s*(3*Dn));
        __nv_bfloat162 kv = *(const __nv_bfloat162*)(qkv + rb + (size_t)s*(3*Dn) + Dn);
        __nv_bfloat162 vv = *(const __nv_bfloat162*)(qkv + rb + (size_t)s*(3*Dn) + 2*Dn);
        q0[s] = __bfloat162float(qv.x); q1[s] = __bfloat162float(qv.y);
        k0[s] = __bfloat162float(kv.x); k1[s] = __bfloat162float(kv.y);
        v0[s] = __bfloat162float(vv.x); v1[s] = __bfloat162float(vv.y);
    }
    float sc[3][3];
    #pragma unroll
    for (int s = 0; s < 3; s++)
        #pragma unroll
        for (int t = 0; t < 3; t++) {
            float p = q0[s]*k0[t] + q1[s]*k1[t];
            // reduce within the 16-lane half (xor 1,2,4,8 stay inside the half)
            p += __shfl_xor_sync(0xffffffffu, p, 1);
            p += __shfl_xor_sync(0xffffffffu, p, 2);
            p += __shfl_xor_sync(0xffffffffu, p, 4);
            p += __shfl_xor_sync(0xffffffffu, p, 8);
            sc[s][t] = p * SCALE_F;
        }
    #pragma unroll
    for (int s = 0; s < 3; s++) {
        float m = fmaxf(sc[s][0], fmaxf(sc[s][1], sc[s][2]));
        float e0 = __expf(sc[s][0]-m);
        float e1 = __expf(sc[s][1]-m);
        float e2 = __expf(sc[s][2]-m);
        float inv = 1.0f/(e0+e1+e2);
        float os0 = (e0*v0[0] + e1*v0[1] + e2*v0[2]) * inv;
        float os1 = (e0*v1[0] + e1*v1[1] + e2*v1[2]) * inv;
        __nv_bfloat162 ov;
        ov.x = __float2bfloat16_rn(os0);
        ov.y = __float2bfloat16_rn(os1);
        *(__nv_bfloat162*)(o + (size_t)(n*3+s)*Dn + h*DHn + 2*l16) = ov;
    }
}

// ---------------- one-shot transpose+convert of all weights (both layers) ----------------
__global__ void transpose_all(const float* __restrict__ Wq, const float* __restrict__ Wk,
                              const float* __restrict__ Wv, const float* __restrict__ Wo,
                              const float* __restrict__ W1, const float* __restrict__ W2,
                              bf16* __restrict__ wt) {
    __shared__ float t[32][33];
    int bid = blockIdx.x;
    int l = bid / 768;
    int tt = bid % 768;
    const float* in; bf16* out; int N, n0, k0, outld;
    if (tt < 192) {
        int which = tt / 64; int q = tt % 64;
        const float* Ws[3] = {Wq, Wk, Wv};
        in = Ws[which] + (size_t)l*Dn*Dn;
        out = wt + (size_t)l*WT_LAYER + which*Dn*Dn;
        N = Dn; outld = Dn;
        n0 = (q & 7) * 32; k0 = (q >> 3) * 32;
    } else if (tt < 256) {
        int q = tt - 192;
        in = Wo + (size_t)l*Dn*Dn;
        out = wt + (size_t)l*WT_LAYER + 196608;
        N = Dn; outld = Dn;
        n0 = (q & 7) * 32; k0 = (q >> 3) * 32;
    } else if (tt < 512) {
        int q = tt - 256;
        in = W1 + (size_t)l*Dn*FFn;
        out = wt + (size_t)l*WT_LAYER + 262144;
        N = FFn; outld = Dn;
        n0 = (q & 31) * 32; k0 = (q >> 5) * 32;
    } else {
        int q = tt - 512;
        in = W2 + (size_t)l*FFn*Dn;
        out = wt + (size_t)l*WT_LAYER + 524288;
        N = Dn; outld = FFn;
        n0 = (q & 7) * 32; k0 = (q >> 3) * 32;
    }
    int tx = threadIdx.x, ty = threadIdx.y;   // 32 x 8
    #pragma unroll
    for (int i = ty; i < 32; i += 8)
        t[i][tx] = in[(size_t)(k0+i)*N + n0+tx];
    __syncthreads();
    #pragma unroll
    for (int i = ty; i < 32; i += 8)
        out[(size_t)(n0+i)*outld + k0+tx] = __float2bfloat16_rn(t[tx][i]);
}

__global__ void concat_bias_kernel(const float* __restrict__ bq, const float* __restrict__ bk,
                                   const float* __restrict__ bv, float* __restrict__ out) {
    int i = blockIdx.x*blockDim.x + threadIdx.x;
    if (i >= 2*3*Dn) return;
    int l = i / (3*Dn);
    int j = i % (3*Dn);
    float v;
    if (j < Dn)        v = bq[l*Dn + j];
    else if (j < 2*Dn) v = bk[l*Dn + j-Dn];
    else               v = bv[l*Dn + j-2*Dn];
    out[i] = v;
}

// ---------------- fused final LN + mean-pool: 1 warp per group ----------------
__global__ void ln_mean_kernel(const float* __restrict__ x,
                               const float* __restrict__ gam,
                               const float* __restrict__ bet,
                               float* __restrict__ out) {
    int warp = (blockIdx.x * blockDim.x + threadIdx.x) >> 5;
    int lane = threadIdx.x & 31;
    if (warp >= NG) return;
    float4 g0 = *(const float4*)(gam + lane*8);
    float4 g1 = *(const float4*)(gam + lane*8 + 4);
    float4 b0 = *(const float4*)(bet + lane*8);
    float4 b1 = *(const float4*)(bet + lane*8 + 4);
    float gs[8] = {g0.x,g0.y,g0.z,g0.w,g1.x,g1.y,g1.z,g1.w};
    float bs[8] = {b0.x,b0.y,b0.z,b0.w,b1.x,b1.y,b1.z,b1.w};
    float avg[8] = {0,0,0,0,0,0,0,0};
    #pragma unroll
    for (int s3 = 0; s3 < 3; s3++) {
        const float* row = x + ((size_t)warp*3 + s3) * Dn;
        float4 a0 = *(const float4*)(row + lane*8);
        float4 a1 = *(const float4*)(row + lane*8 + 4);
        float vals[8] = {a0.x,a0.y,a0.z,a0.w,a1.x,a1.y,a1.z,a1.w};
        float s = 0.f, sq = 0.f;
        #pragma unroll
        for (int i = 0; i < 8; i++) { s += vals[i]; sq += vals[i]*vals[i]; }
        #pragma unroll
        for (int o = 16; o > 0; o >>= 1) {
            s  += __shfl_xor_sync(0xffffffffu, s,  o);
            sq += __shfl_xor_sync(0xffffffffu, sq, o);
        }
        float mean = s * (1.0f/Dn);
        float var  = sq * (1.0f/Dn) - mean*mean;
        float rstd = rsqrtf(var + 1e-5f);
        #pragma unroll
        for (int i = 0; i < 8; i++)
            avg[i] += ((vals[i]-mean)*rstd*gs[i] + bs[i]) * (1.0f/3.0f);
    }
    float* orow = out + (size_t)warp * Dn;
    *(float4*)(orow + lane*8)     = make_float4(avg[0],avg[1],avg[2],avg[3]);
    *(float4*)(orow + lane*8 + 4) = make_float4(avg[4],avg[5],avg[6],avg[7]);
}

// ---------------- host ----------------
extern "C" void kernel_launch(void* const* d_in, const int* in_sizes, int n_in,
                              void* d_out, int out_size) {
    const float* term  = (const float*)d_in[0];
    const float* pred  = (const float*)d_in[1];
    const float* Wq    = (const float*)d_in[2];
    const float* Wk    = (const float*)d_in[3];
    const float* Wv    = (const float*)d_in[4];
    const float* Wo    = (const float*)d_in[5];
    const float* bq    = (const float*)d_in[6];
    const float* bk    = (const float*)d_in[7];
    const float* bv    = (const float*)d_in[8];
    const float* bo    = (const float*)d_in[9];
    const float* ln1g  = (const float*)d_in[10];
    const float* ln1b  = (const float*)d_in[11];
    const float* ln2g  = (const float*)d_in[12];
    const float* ln2b  = (const float*)d_in[13];
    const float* W1    = (const float*)d_in[14];
    const float* b1    = (const float*)d_in[15];
    const float* W2    = (const float*)d_in[16];
    const float* b2    = (const float*)d_in[17];
    const float* lnfg  = (const float*)d_in[18];
    const float* lnfb  = (const float*)d_in[19];
    float* out = (float*)d_out;

    float *x, *bqkv;
    bf16 *h, *qkv, *o, *f, *wt;
    cudaGetSymbolAddress((void**)&x,   g_x);
    cudaGetSymbolAddress((void**)&h,   g_h);
    cudaGetSymbolAddress((void**)&qkv, g_qkv);
    cudaGetSymbolAddress((void**)&o,   g_o);
    cudaGetSymbolAddress((void**)&f,   g_f);
    cudaGetSymbolAddress((void**)&wt,  g_wt);
    cudaGetSymbolAddress((void**)&bqkv,g_bqkv);

    cudaFuncSetAttribute(gemm_tc_sm<0,false,true >, cudaFuncAttributeMaxDynamicSharedMemorySize, SM_SMEM_BYTES);
    cudaFuncSetAttribute(gemm_tc_sm<1,false,true >, cudaFuncAttributeMaxDynamicSharedMemorySize, SM_SMEM_BYTES);
    cudaFuncSetAttribute(gemm_tc_sm<0,true ,false>, cudaFuncAttributeMaxDynamicSharedMemorySize, SM_SMEM_BYTES);
    cudaFuncSetAttribute(gemm_tc_pe, cudaFuncAttributeMaxDynamicSharedMemorySize, PE_SMEM_BYTES);

    // weight prep + fused build_x + LN1(layer0)
    transpose_all<<<2*768, dim3(32,8)>>>(Wq, Wk, Wv, Wo, W1, W2, wt);
    concat_bias_kernel<<<6, 256>>>(bq, bk, bv, bqkv);
    build_ln_kernel<<<MROWS/8, 256>>>(term, pred, ln1g, ln1b, x, h);

    const int MB  = MROWS / 128;        // 1152
    const int MBP = MB / TPB;           // 288
    for (int l = 0; l < NLn; l++) {
        const bf16* wl = wt + (size_t)l*WT_LAYER;

        // fused QKV GEMM (small kernel, 2 CTAs/SM): [MROWS,256] @ [256,768]
        gemm_tc_sm<0,false,true><<<dim3(6, MB), 128, SM_SMEM_BYTES>>>(
            h, Dn, wl, bqkv + l*3*Dn, nullptr, qkv, 3*Dn, Dn);

        // attention (v2: 1 warp per head-pair)
        attn_kernel<<<NG*(Hn/2)/8, 256>>>(qkv, o);

        // output projection + residual + fused LN2 (persistent-B EPILN)
        gemm_tc_pe<<<dim3(1, MBP), 256, PE_SMEM_BYTES>>>(
            o, Dn, wl + 196608, bo + l*Dn, x, x, Dn,
            ln2g + l*Dn, ln2b + l*Dn, h);

        // FFN up (relu, small kernel): [MROWS,256] @ [256,1024]
        gemm_tc_sm<1,false,true><<<dim3(8, MB), 128, SM_SMEM_BYTES>>>(
            h, Dn, wl + 262144, b1 + l*FFn, nullptr, f, FFn, Dn);

        // FFN down + residual -> x fp32 (small kernel, 2 CTAs/SM)
        gemm_tc_sm<0,true,false><<<dim3(2, MB), 128, SM_SMEM_BYTES>>>(
            f, FFn, wl + 524288, b2 + l*Dn, x, x, Dn, FFn);

        // LN1 of next layer (standalone)
        if (l + 1 < NLn)
            ln_kernel<<<MROWS/8, 256>>>(x, ln1g + (l+1)*Dn, ln1b + (l+1)*Dn, h);
    }

    // fused final LN + mean pool
    ln_mean_kernel<<<NG/8, 256>>>(x, lnfg, lnfb, out);
    (void)in_sizes; (void)n_in; (void)out_size;
}